// round 2
// baseline (speedup 1.0000x reference)
#include <cuda_runtime.h>
#include <math.h>

#define NN 50000
#define EE 1000000
#define NIN 1281
#define HH 256
#define LL 4
#define KPAD 288   // 256 Hsum + 3 sh + 16 radial + 1 deg + 12 zero pad

// ---------------- scratch (device globals; no runtime allocation) ----------------
__device__ float g_t1[NN * HH];        // node-encoder intermediate
__device__ float g_h[NN * HH];         // node embeddings
__device__ float g_Abuf[NN * KPAD];    // [Hsum | EF_agg | deg | 0pad]
__device__ float g_agg[NN * HH];       // GEMM outputs
__device__ float g_gatev[NN * 64];     // pool gate hidden
__device__ float g_gate[NN];
__device__ float g_e[NN];
__device__ int   g_deg[NN];
__device__ int   g_rowptr[NN + 1];
__device__ int   g_cursor[NN];
__device__ int   g_csrc[EE];
__device__ float g_Wpack[LL * KPAD * HH];
__device__ float g_partial[256];
__device__ float g_scal[4];            // [0]=max gate, [1]=sumExp
__device__ float g_Gvec[HH];

// ---------------- helpers ----------------
__device__ __forceinline__ float warp_sum(float v) {
    #pragma unroll
    for (int o = 16; o; o >>= 1) v += __shfl_xor_sync(0xffffffffu, v, o);
    return v;
}
__device__ __forceinline__ float silu_f(float x) { return x / (1.f + expf(-x)); }

// ---------------- setup kernels ----------------
__global__ void zero_kernel() {
    int i = blockIdx.x * 256 + threadIdx.x;
    if (i < NN) {
        g_deg[i] = 0;
        g_cursor[i] = 0;
        float* p = g_Abuf + (long)i * KPAD + 256;
        #pragma unroll
        for (int j = 0; j < 32; j++) p[j] = 0.f;
    }
    if (i < HH) g_Gvec[i] = 0.f;
    if (i < 4) g_scal[i] = 0.f;
}

// pass 1: degree histogram + aggregate edge features (sh, radial) into Abuf cols 256..274
__global__ void edge1_kernel(const int* __restrict__ ei, const float* __restrict__ pos) {
    int e = blockIdx.x * 256 + threadIdx.x;
    if (e >= EE) return;
    int s = ei[e];
    int d = ei[EE + e];
    atomicAdd(&g_deg[d], 1);
    float rx = pos[3 * d + 0] - pos[3 * s + 0];
    float ry = pos[3 * d + 1] - pos[3 * s + 1];
    float rz = pos[3 * d + 2] - pos[3 * s + 2];
    float dist = sqrtf(rx * rx + ry * ry + rz * rz);
    float inv = 1.f / fmaxf(dist, 1e-12f);
    float* ab = g_Abuf + (long)d * KPAD + 256;
    atomicAdd(ab + 0, rx * inv);
    atomicAdd(ab + 1, ry * inv);
    atomicAdd(ab + 2, rz * inv);
    const float width = 0.1953125f;  // 0.5*(10/16)^2
    #pragma unroll
    for (int j = 0; j < 16; j++) {
        float c = (10.f / 15.f) * (float)j;
        float t = dist - c;
        atomicAdd(ab + 3 + j, expf(-width * t * t));
    }
}

// single-block exclusive scan of g_deg -> g_rowptr
__global__ void scan_kernel() {
    __shared__ int s[1024];
    __shared__ int carry;
    int tid = threadIdx.x;
    if (tid == 0) { carry = 0; g_rowptr[0] = 0; }
    __syncthreads();
    for (int base = 0; base < NN; base += 1024) {
        int v = (base + tid < NN) ? g_deg[base + tid] : 0;
        s[tid] = v;
        __syncthreads();
        for (int off = 1; off < 1024; off <<= 1) {
            int t = (tid >= off) ? s[tid - off] : 0;
            __syncthreads();
            s[tid] += t;
            __syncthreads();
        }
        if (base + tid < NN) g_rowptr[base + tid + 1] = carry + s[tid];
        __syncthreads();
        if (tid == 0) carry += s[1023];
        __syncthreads();
    }
}

__global__ void deg2abuf_kernel() {
    int n = blockIdx.x * 256 + threadIdx.x;
    if (n < NN) g_Abuf[(long)n * KPAD + 275] = (float)g_deg[n];
}

// pass 2: fill CSR src lists
__global__ void edge2_kernel(const int* __restrict__ ei) {
    int e = blockIdx.x * 256 + threadIdx.x;
    if (e >= EE) return;
    int s = ei[e];
    int d = ei[EE + e];
    int slot = atomicAdd(&g_cursor[d], 1);
    g_csrc[g_rowptr[d] + slot] = s;
}

// pack conv weights: rows 0..274 = convW[l], row 275 = convB[l], 276..287 = 0
__global__ void pack_kernel(const float* __restrict__ convW, const float* __restrict__ convB) {
    int idx = blockIdx.x * 256 + threadIdx.x;
    const int total = LL * KPAD * HH;
    if (idx >= total) return;
    int l = idx / (KPAD * HH);
    int r = (idx / HH) % KPAD;
    int c = idx % HH;
    float v = 0.f;
    if (r < 275)      v = convW[((long)l * 275 + r) * HH + c];
    else if (r == 275) v = convB[l * HH + c];
    g_Wpack[idx] = v;
}

// ---------------- SGEMM: C = act(A@B + bias), BM=BN=128, BK=8, 8x8 microtile ----------------
__global__ __launch_bounds__(256, 2)
void sgemm_kernel(const float* __restrict__ A, int lda,
                  const float* __restrict__ B, int ldb,
                  const float* __restrict__ bias,
                  float* __restrict__ C, int ldc,
                  int M, int Ncols, int K, int act) {
    __shared__ float As[8][128];
    __shared__ float Bs[8][128];
    int t = threadIdx.x;
    int ty = t >> 4, tx = t & 15;
    int rowBase = blockIdx.x * 128;
    int colBase = blockIdx.y * 128;

    float acc[8][8];
    #pragma unroll
    for (int i = 0; i < 8; i++)
        #pragma unroll
        for (int j = 0; j < 8; j++) acc[i][j] = 0.f;

    int arow = t >> 1;         // 0..127
    int ak0 = (t & 1) * 4;     // 0 or 4
    int bk  = t >> 5;          // 0..7
    int bc  = (t & 31) * 4;    // 0..124

    for (int k0 = 0; k0 < K; k0 += 8) {
        // load A tile (scalar, coalesced at 16B granularity, transposed into smem)
        {
            int gr = rowBase + arow;
            #pragma unroll
            for (int j = 0; j < 4; j++) {
                int kk = ak0 + j;
                int gk = k0 + kk;
                float v = 0.f;
                if (gr < M && gk < K) v = A[(long)gr * lda + gk];
                As[kk][arow] = v;
            }
        }
        // load B tile (float4)
        {
            int gk = k0 + bk;
            int gc = colBase + bc;
            float4 v = make_float4(0.f, 0.f, 0.f, 0.f);
            if (gk < K && gc < Ncols)
                v = *(const float4*)(B + (long)gk * ldb + gc);
            Bs[bk][bc + 0] = v.x; Bs[bk][bc + 1] = v.y;
            Bs[bk][bc + 2] = v.z; Bs[bk][bc + 3] = v.w;
        }
        __syncthreads();
        #pragma unroll
        for (int kk = 0; kk < 8; kk++) {
            float a[8], b[8];
            float4 a0 = *(const float4*)&As[kk][ty * 8];
            float4 a1 = *(const float4*)&As[kk][ty * 8 + 4];
            float4 b0 = *(const float4*)&Bs[kk][tx * 8];
            float4 b1 = *(const float4*)&Bs[kk][tx * 8 + 4];
            a[0] = a0.x; a[1] = a0.y; a[2] = a0.z; a[3] = a0.w;
            a[4] = a1.x; a[5] = a1.y; a[6] = a1.z; a[7] = a1.w;
            b[0] = b0.x; b[1] = b0.y; b[2] = b0.z; b[3] = b0.w;
            b[4] = b1.x; b[5] = b1.y; b[6] = b1.z; b[7] = b1.w;
            #pragma unroll
            for (int i = 0; i < 8; i++)
                #pragma unroll
                for (int j = 0; j < 8; j++)
                    acc[i][j] += a[i] * b[j];
        }
        __syncthreads();
    }
    #pragma unroll
    for (int i = 0; i < 8; i++) {
        int r = rowBase + ty * 8 + i;
        if (r >= M) continue;
        #pragma unroll
        for (int j = 0; j < 8; j++) {
            int c = colBase + tx * 8 + j;
            if (c >= Ncols) continue;
            float v = acc[i][j] + (bias ? bias[c] : 0.f);
            if (act) v = silu_f(v);
            C[(long)r * ldc + c] = v;
        }
    }
}

// ---------------- LayerNorm (warp per row of 256) ----------------
__global__ void ln_kernel(const float* __restrict__ in, const float* __restrict__ g,
                          const float* __restrict__ b, float* __restrict__ out, int M) {
    int w = (blockIdx.x * blockDim.x + threadIdx.x) >> 5;
    int lane = threadIdx.x & 31;
    if (w >= M) return;
    const float* ip = in + (long)w * HH;
    float x[8];
    float s = 0.f;
    #pragma unroll
    for (int i = 0; i < 8; i++) { x[i] = ip[lane + 32 * i]; s += x[i]; }
    s = warp_sum(s);
    float m = s * (1.f / 256.f);
    float q = 0.f;
    #pragma unroll
    for (int i = 0; i < 8; i++) { float d = x[i] - m; q += d * d; }
    q = warp_sum(q);
    float rs = rsqrtf(q * (1.f / 256.f) + 1e-5f);
    float* op = out + (long)w * HH;
    #pragma unroll
    for (int i = 0; i < 8; i++) {
        int c = lane + 32 * i;
        op[c] = (x[i] - m) * rs * g[c] + b[c];
    }
}

// ---------------- gather: Hsum[n] = sum_e h[src_e]  (warp per node, float4) ----------------
__global__ void gather_kernel() {
    int w = (blockIdx.x * 256 + threadIdx.x) >> 5;
    int lane = threadIdx.x & 31;
    if (w >= NN) return;
    float4 a0 = make_float4(0.f, 0.f, 0.f, 0.f);
    float4 a1 = make_float4(0.f, 0.f, 0.f, 0.f);
    int beg = g_rowptr[w], end = g_rowptr[w + 1];
    for (int e = beg; e < end; e++) {
        int s = g_csrc[e];
        const float4* hp = (const float4*)(g_h + (long)s * HH);
        float4 v0 = hp[lane];
        float4 v1 = hp[lane + 32];
        a0.x += v0.x; a0.y += v0.y; a0.z += v0.z; a0.w += v0.w;
        a1.x += v1.x; a1.y += v1.y; a1.z += v1.z; a1.w += v1.w;
    }
    float4* ap = (float4*)(g_Abuf + (long)w * KPAD);
    ap[lane] = a0;
    ap[lane + 32] = a1;
}

// ---------------- post-conv: h = LN(h + LN(silu(agg))) (warp per row) ----------------
__global__ void postconv_kernel(const float* __restrict__ cg, const float* __restrict__ cb,
                                const float* __restrict__ lg, const float* __restrict__ lb) {
    int w = (blockIdx.x * 256 + threadIdx.x) >> 5;
    int lane = threadIdx.x & 31;
    if (w >= NN) return;
    const float* ap = g_agg + (long)w * HH;
    float* hp = g_h + (long)w * HH;
    float x[8];
    float s = 0.f;
    #pragma unroll
    for (int i = 0; i < 8; i++) {
        float a = ap[lane + 32 * i];
        float v = silu_f(a);
        x[i] = v; s += v;
    }
    s = warp_sum(s);
    float m1 = s * (1.f / 256.f);
    float q = 0.f;
    #pragma unroll
    for (int i = 0; i < 8; i++) { float d = x[i] - m1; q += d * d; }
    q = warp_sum(q);
    float rs1 = rsqrtf(q * (1.f / 256.f) + 1e-5f);
    float z[8];
    float s2 = 0.f;
    #pragma unroll
    for (int i = 0; i < 8; i++) {
        int c = lane + 32 * i;
        float y = (x[i] - m1) * rs1 * cg[c] + cb[c];
        float zz = hp[c] + y;
        z[i] = zz; s2 += zz;
    }
    s2 = warp_sum(s2);
    float m2 = s2 * (1.f / 256.f);
    float q2 = 0.f;
    #pragma unroll
    for (int i = 0; i < 8; i++) { float d = z[i] - m2; q2 += d * d; }
    q2 = warp_sum(q2);
    float rs2 = rsqrtf(q2 * (1.f / 256.f) + 1e-5f);
    #pragma unroll
    for (int i = 0; i < 8; i++) {
        int c = lane + 32 * i;
        hp[c] = (z[i] - m2) * rs2 * lg[c] + lb[c];
    }
}

// ---------------- pooling ----------------
__global__ void gate_kernel(const float* __restrict__ pgW2, const float* __restrict__ pgb2) {
    int w = (blockIdx.x * 256 + threadIdx.x) >> 5;
    int lane = threadIdx.x & 31;
    if (w >= NN) return;
    float v = g_gatev[(long)w * 64 + lane] * pgW2[lane]
            + g_gatev[(long)w * 64 + 32 + lane] * pgW2[32 + lane];
    v = warp_sum(v);
    if (lane == 0) g_gate[w] = v + pgb2[0];
}

__global__ void maxpart_kernel() {
    __shared__ float sm[256];
    int tid = threadIdx.x;
    float m = -1e30f;
    for (int i = blockIdx.x * 256 + tid; i < NN; i += gridDim.x * 256)
        m = fmaxf(m, g_gate[i]);
    sm[tid] = m;
    __syncthreads();
    for (int o = 128; o; o >>= 1) {
        if (tid < o) sm[tid] = fmaxf(sm[tid], sm[tid + o]);
        __syncthreads();
    }
    if (tid == 0) g_partial[blockIdx.x] = sm[0];
}

__global__ void maxfin_kernel(int nb) {
    __shared__ float sm[256];
    int tid = threadIdx.x;
    sm[tid] = (tid < nb) ? g_partial[tid] : -1e30f;
    __syncthreads();
    for (int o = 128; o; o >>= 1) {
        if (tid < o) sm[tid] = fmaxf(sm[tid], sm[tid + o]);
        __syncthreads();
    }
    if (tid == 0) g_scal[0] = sm[0];
}

__global__ void expsum_kernel() {
    __shared__ float sm[256];
    int tid = threadIdx.x;
    int i = blockIdx.x * 256 + tid;
    float M = g_scal[0];
    float e = 0.f;
    if (i < NN) { e = expf(g_gate[i] - M); g_e[i] = e; }
    sm[tid] = e;
    __syncthreads();
    for (int o = 128; o; o >>= 1) {
        if (tid < o) sm[tid] += sm[tid + o];
        __syncthreads();
    }
    if (tid == 0) atomicAdd(&g_scal[1], sm[0]);
}

__global__ void wsum_kernel() {
    int t = threadIdx.x;
    int n0 = blockIdx.x * 256;
    float acc = 0.f;
    for (int i = 0; i < 256; i++) {
        int n = n0 + i;
        if (n >= NN) break;
        acc += g_e[n] * g_h[(long)n * HH + t];
    }
    atomicAdd(&g_Gvec[t], acc);
}

// ---------------- heads (single block) ----------------
__global__ void heads_kernel(const float* __restrict__ clW1, const float* __restrict__ clb1,
                             const float* __restrict__ clW2, const float* __restrict__ clb2,
                             const float* __restrict__ prW1, const float* __restrict__ prb1,
                             const float* __restrict__ prW2, const float* __restrict__ prb2,
                             float* __restrict__ out) {
    __shared__ float emb[256], c1[128], p1[256], pr[128];
    __shared__ float nrm;
    int t = threadIdx.x;
    float se = g_scal[1];
    float ev = g_Gvec[t] / se;
    emb[t] = ev;
    out[132 + t] = ev;   // graph_emb at [132..388)
    __syncthreads();
    if (t < 128) {
        float a = 0.f;
        for (int k = 0; k < 256; k++) a += emb[k] * clW1[k * 128 + t];
        a += clb1[t];
        c1[t] = silu_f(a);
    }
    {
        float a = 0.f;
        for (int k = 0; k < 256; k++) a += emb[k] * prW1[k * 256 + t];
        a += prb1[t];
        p1[t] = silu_f(a);
    }
    __syncthreads();
    if (t < 4) {
        float a = 0.f;
        for (int k = 0; k < 128; k++) a += c1[k] * clW2[k * 4 + t];
        out[t] = a + clb2[t];            // logits at [0..4)
    }
    if (t < 128) {
        float a = 0.f;
        for (int k = 0; k < 256; k++) a += p1[k] * prW2[k * 128 + t];
        pr[t] = a + prb2[t];
    }
    __syncthreads();
    if (t == 0) {
        float s = 0.f;
        for (int k = 0; k < 128; k++) s += pr[k] * pr[k];
        nrm = fmaxf(sqrtf(s), 1e-12f);
    }
    __syncthreads();
    if (t < 128) out[4 + t] = pr[t] / nrm;  // proj at [4..132)
}

// ---------------- launch ----------------
extern "C" void kernel_launch(void* const* d_in, const int* in_sizes, int n_in,
                              void* d_out, int out_size) {
    const float* x       = (const float*)d_in[0];
    const float* pos     = (const float*)d_in[1];
    const int*   ei      = (const int*)d_in[2];
    const float* ne_W1   = (const float*)d_in[3];
    const float* ne_b1   = (const float*)d_in[4];
    const float* ne_W2   = (const float*)d_in[5];
    const float* ne_b2   = (const float*)d_in[6];
    const float* ne_g    = (const float*)d_in[7];
    const float* ne_beta = (const float*)d_in[8];
    const float* convW   = (const float*)d_in[9];
    const float* convB   = (const float*)d_in[10];
    const float* convG   = (const float*)d_in[11];
    const float* convBeta= (const float*)d_in[12];
    const float* lnG     = (const float*)d_in[13];
    const float* lnB     = (const float*)d_in[14];
    const float* pgW1    = (const float*)d_in[15];
    const float* pgb1    = (const float*)d_in[16];
    const float* pgW2    = (const float*)d_in[17];
    const float* pgb2    = (const float*)d_in[18];
    const float* clW1    = (const float*)d_in[19];
    const float* clb1    = (const float*)d_in[20];
    const float* clW2    = (const float*)d_in[21];
    const float* clb2    = (const float*)d_in[22];
    const float* prW1    = (const float*)d_in[23];
    const float* prb1    = (const float*)d_in[24];
    const float* prW2    = (const float*)d_in[25];
    const float* prb2    = (const float*)d_in[26];
    float* out = (float*)d_out;

    float *p_t1, *p_h, *p_Abuf, *p_agg, *p_gatev, *p_Wpack;
    cudaGetSymbolAddress((void**)&p_t1, g_t1);
    cudaGetSymbolAddress((void**)&p_h, g_h);
    cudaGetSymbolAddress((void**)&p_Abuf, g_Abuf);
    cudaGetSymbolAddress((void**)&p_agg, g_agg);
    cudaGetSymbolAddress((void**)&p_gatev, g_gatev);
    cudaGetSymbolAddress((void**)&p_Wpack, g_Wpack);

    const int EB = (EE + 255) / 256;
    const int NB = (NN + 255) / 256;
    const int WB = (NN + 7) / 8;          // warp-per-row blocks (256 thr = 8 warps)
    const int MB = (NN + 127) / 128;      // 391

    // setup (once per launch; edges/pos layer-invariant)
    zero_kernel<<<NB, 256>>>();
    edge1_kernel<<<EB, 256>>>(ei, pos);
    scan_kernel<<<1, 1024>>>();
    deg2abuf_kernel<<<NB, 256>>>();
    edge2_kernel<<<EB, 256>>>(ei);
    pack_kernel<<<(LL * KPAD * HH + 255) / 256, 256>>>(convW, convB);

    // node encoder
    sgemm_kernel<<<dim3(MB, 2), 256>>>(x, NIN, ne_W1, HH, ne_b1, p_t1, HH, NN, HH, NIN, 1);
    sgemm_kernel<<<dim3(MB, 2), 256>>>(p_t1, HH, ne_W2, HH, ne_b2, p_agg, HH, NN, HH, HH, 0);
    ln_kernel<<<WB, 256>>>(p_agg, ne_g, ne_beta, p_h, NN);

    // conv layers
    for (int l = 0; l < LL; l++) {
        gather_kernel<<<WB, 256>>>();
        sgemm_kernel<<<dim3(MB, 2), 256>>>(p_Abuf, KPAD, p_Wpack + (long)l * KPAD * HH, HH,
                                           nullptr, p_agg, HH, NN, HH, KPAD, 0);
        postconv_kernel<<<WB, 256>>>(convG + l * HH, convBeta + l * HH,
                                     lnG + l * HH, lnB + l * HH);
    }

    // attention pooling
    sgemm_kernel<<<dim3(MB, 1), 256>>>(p_h, HH, pgW1, 64, pgb1, p_gatev, 64, NN, 64, HH, 1);
    gate_kernel<<<WB, 256>>>(pgW2, pgb2);
    maxpart_kernel<<<64, 256>>>();
    maxfin_kernel<<<1, 256>>>(64);
    expsum_kernel<<<NB, 256>>>();
    wsum_kernel<<<NB, 256>>>();

    // heads
    heads_kernel<<<1, 256>>>(clW1, clb1, clW2, clb2, prW1, prb1, prW2, prb2, out);
}

// round 3
// speedup vs baseline: 1.6657x; 1.6657x over previous
#include <cuda_runtime.h>
#include <math.h>

#define NN 50000
#define EE 1000000
#define NIN 1281
#define HH 256
#define LL 4
#define KPAD 288   // 256 Hsum + 3 sh + 16 radial + 1 deg + 12 zero pad

// ---------------- scratch (device globals; no runtime allocation) ----------------
__device__ float g_t1[NN * HH];        // node-encoder intermediate
__device__ float g_h[NN * HH];         // node embeddings
__device__ float g_Abuf[NN * KPAD];    // [Hsum | EF_agg | deg | 0pad]
__device__ float g_agg[NN * HH];       // GEMM outputs
__device__ float g_gatev[NN * 64];     // pool gate hidden
__device__ float g_gate[NN];
__device__ float g_e[NN];
__device__ int   g_deg[NN];
__device__ int   g_rowptr[NN + 1];
__device__ int   g_cursor[NN];
__device__ int   g_csrc[EE];
__device__ float g_Wpack[LL * KPAD * HH];
__device__ float g_partial[256];
__device__ float g_scal[4];            // [0]=max gate, [1]=sumExp
__device__ float g_Gvec[HH];

// ---------------- helpers ----------------
__device__ __forceinline__ float warp_sum(float v) {
    #pragma unroll
    for (int o = 16; o; o >>= 1) v += __shfl_xor_sync(0xffffffffu, v, o);
    return v;
}
__device__ __forceinline__ float silu_f(float x) { return x / (1.f + expf(-x)); }
__device__ __forceinline__ unsigned f2tf(float f) {
    unsigned r;
    asm("cvt.rna.tf32.f32 %0, %1;" : "=r"(r) : "f"(f));
    return r;
}

// ---------------- setup kernels ----------------
__global__ void zero_kernel() {
    int i = blockIdx.x * 256 + threadIdx.x;
    if (i < NN) { g_deg[i] = 0; g_cursor[i] = 0; }
    if (i < HH) g_Gvec[i] = 0.f;
    if (i < 4) g_scal[i] = 0.f;
}

// pass 1: degree histogram only
__global__ void edge1_kernel(const int* __restrict__ ei) {
    int e = blockIdx.x * 256 + threadIdx.x;
    if (e >= EE) return;
    atomicAdd(&g_deg[ei[EE + e]], 1);
}

// single-block exclusive scan of g_deg -> g_rowptr
__global__ void scan_kernel() {
    __shared__ int s[1024];
    __shared__ int carry;
    int tid = threadIdx.x;
    if (tid == 0) { carry = 0; g_rowptr[0] = 0; }
    __syncthreads();
    for (int base = 0; base < NN; base += 1024) {
        int v = (base + tid < NN) ? g_deg[base + tid] : 0;
        s[tid] = v;
        __syncthreads();
        for (int off = 1; off < 1024; off <<= 1) {
            int t = (tid >= off) ? s[tid - off] : 0;
            __syncthreads();
            s[tid] += t;
            __syncthreads();
        }
        if (base + tid < NN) g_rowptr[base + tid + 1] = carry + s[tid];
        __syncthreads();
        if (tid == 0) carry += s[1023];
        __syncthreads();
    }
}

// pass 2: fill CSR src lists
__global__ void edge2_kernel(const int* __restrict__ ei) {
    int e = blockIdx.x * 256 + threadIdx.x;
    if (e >= EE) return;
    int s = ei[e];
    int d = ei[EE + e];
    int slot = atomicAdd(&g_cursor[d], 1);
    g_csrc[g_rowptr[d] + slot] = s;
}

// per-node edge-feature aggregation (no atomics): Abuf cols 256..287
__global__ void ef_kernel(const float* __restrict__ pos) {
    int n = blockIdx.x * 256 + threadIdx.x;
    if (n >= NN) return;
    float px = pos[3 * n + 0], py = pos[3 * n + 1], pz = pos[3 * n + 2];
    float shx = 0.f, shy = 0.f, shz = 0.f;
    float rad[16];
    #pragma unroll
    for (int j = 0; j < 16; j++) rad[j] = 0.f;
    int beg = g_rowptr[n], end = g_rowptr[n + 1];
    const float width = 0.1953125f;  // 0.5*(10/16)^2
    for (int e = beg; e < end; e++) {
        int s = g_csrc[e];
        float rx = px - pos[3 * s + 0];
        float ry = py - pos[3 * s + 1];
        float rz = pz - pos[3 * s + 2];
        float dist = sqrtf(rx * rx + ry * ry + rz * rz);
        float inv = 1.f / fmaxf(dist, 1e-12f);
        shx += rx * inv; shy += ry * inv; shz += rz * inv;
        #pragma unroll
        for (int j = 0; j < 16; j++) {
            float t = dist - (10.f / 15.f) * (float)j;
            rad[j] += expf(-width * t * t);
        }
    }
    float* ab = g_Abuf + (long)n * KPAD + 256;
    ab[0] = shx; ab[1] = shy; ab[2] = shz;
    #pragma unroll
    for (int j = 0; j < 16; j++) ab[3 + j] = rad[j];
    ab[19] = (float)(end - beg);     // deg column (row 275)
    #pragma unroll
    for (int j = 20; j < 32; j++) ab[j] = 0.f;
}

// pack conv weights: rows 0..274 = convW[l], row 275 = convB[l], 276..287 = 0
__global__ void pack_kernel(const float* __restrict__ convW, const float* __restrict__ convB) {
    int idx = blockIdx.x * 256 + threadIdx.x;
    const int total = LL * KPAD * HH;
    if (idx >= total) return;
    int l = idx / (KPAD * HH);
    int r = (idx / HH) % KPAD;
    int c = idx % HH;
    float v = 0.f;
    if (r < 275)      v = convW[((long)l * 275 + r) * HH + c];
    else if (r == 275) v = convB[l * HH + c];
    g_Wpack[idx] = v;
}

// ---------------- TF32 MMA GEMM: C = act(A@B + bias) ----------------
// BM=128, BN=128, BK=32; 8 warps (2x4); warp tile 64x32; mma m16n8k8 tf32
__global__ __launch_bounds__(256, 2)
void mma_gemm_kernel(const float* __restrict__ A, int lda,
                     const float* __restrict__ B, int ldb,
                     const float* __restrict__ bias,
                     float* __restrict__ C, int ldc,
                     int M, int Ncols, int K, int act) {
    __shared__ unsigned As[128][36];   // [row][k], tf32 bits
    __shared__ unsigned Bs[32][136];   // [k][col], tf32 bits
    int t = threadIdx.x;
    int lane = t & 31, warp = t >> 5;
    int wr = warp >> 2;     // 0..1
    int wc = warp & 3;      // 0..3
    int rowBase = blockIdx.x * 128;
    int colBase = blockIdx.y * 128;

    float acc[4][4][4];
    #pragma unroll
    for (int mi = 0; mi < 4; mi++)
        #pragma unroll
        for (int ni = 0; ni < 4; ni++)
            #pragma unroll
            for (int q = 0; q < 4; q++) acc[mi][ni][q] = 0.f;

    int aRow = t >> 1;            // 0..127
    int aK0 = (t & 1) * 16;       // 0 or 16
    int bK = t >> 3;              // 0..31
    int bN0 = (t & 7) * 16;       // 0..112

    int gr = rowBase + aRow;
    const float* Arow = A + (long)gr * lda;

    for (int k0 = 0; k0 < K; k0 += 32) {
        // load A tile (scalar loads: lda may be odd), convert to tf32
        #pragma unroll
        for (int v = 0; v < 16; v++) {
            int gk = k0 + aK0 + v;
            float x = 0.f;
            if (gr < M && gk < K) x = Arow[gk];
            As[aRow][aK0 + v] = f2tf(x);
        }
        // load B tile (float4; ldb multiple of 16 floats here), convert
        {
            int gk = k0 + bK;
            int gc = colBase + bN0;
            #pragma unroll
            for (int v = 0; v < 4; v++) {
                float4 d = make_float4(0.f, 0.f, 0.f, 0.f);
                if (gk < K && gc + v * 4 < Ncols)
                    d = *(const float4*)(B + (long)gk * ldb + gc + v * 4);
                Bs[bK][bN0 + v * 4 + 0] = f2tf(d.x);
                Bs[bK][bN0 + v * 4 + 1] = f2tf(d.y);
                Bs[bK][bN0 + v * 4 + 2] = f2tf(d.z);
                Bs[bK][bN0 + v * 4 + 3] = f2tf(d.w);
            }
        }
        __syncthreads();
        #pragma unroll
        for (int kk = 0; kk < 4; kk++) {
            int ko = kk * 8;
            unsigned af[4][4], bf[4][2];
            #pragma unroll
            for (int mi = 0; mi < 4; mi++) {
                int ar = wr * 64 + mi * 16 + (lane >> 2);
                af[mi][0] = As[ar][ko + (lane & 3)];
                af[mi][1] = As[ar + 8][ko + (lane & 3)];
                af[mi][2] = As[ar][ko + (lane & 3) + 4];
                af[mi][3] = As[ar + 8][ko + (lane & 3) + 4];
            }
            #pragma unroll
            for (int ni = 0; ni < 4; ni++) {
                int bn = wc * 32 + ni * 8 + (lane >> 2);
                bf[ni][0] = Bs[ko + (lane & 3)][bn];
                bf[ni][1] = Bs[ko + (lane & 3) + 4][bn];
            }
            #pragma unroll
            for (int mi = 0; mi < 4; mi++)
                #pragma unroll
                for (int ni = 0; ni < 4; ni++) {
                    asm volatile(
                        "mma.sync.aligned.m16n8k8.row.col.f32.tf32.tf32.f32 "
                        "{%0,%1,%2,%3}, {%4,%5,%6,%7}, {%8,%9}, {%0,%1,%2,%3};"
                        : "+f"(acc[mi][ni][0]), "+f"(acc[mi][ni][1]),
                          "+f"(acc[mi][ni][2]), "+f"(acc[mi][ni][3])
                        : "r"(af[mi][0]), "r"(af[mi][1]), "r"(af[mi][2]), "r"(af[mi][3]),
                          "r"(bf[ni][0]), "r"(bf[ni][1]));
                }
        }
        __syncthreads();
    }

    // epilogue
    #pragma unroll
    for (int mi = 0; mi < 4; mi++) {
        #pragma unroll
        for (int ni = 0; ni < 4; ni++) {
            int r0 = rowBase + wr * 64 + mi * 16 + (lane >> 2);
            int c0 = colBase + wc * 32 + ni * 8 + (lane & 3) * 2;
            #pragma unroll
            for (int half = 0; half < 2; half++) {
                int r = r0 + half * 8;
                if (r >= M) continue;
                #pragma unroll
                for (int q = 0; q < 2; q++) {
                    int c = c0 + q;
                    if (c >= Ncols) continue;
                    float v = acc[mi][ni][half * 2 + q] + (bias ? bias[c] : 0.f);
                    if (act) v = silu_f(v);
                    C[(long)r * ldc + c] = v;
                }
            }
        }
    }
}

// ---------------- LayerNorm (warp per row of 256) ----------------
__global__ void ln_kernel(const float* __restrict__ in, const float* __restrict__ g,
                          const float* __restrict__ b, float* __restrict__ out, int M) {
    int w = (blockIdx.x * blockDim.x + threadIdx.x) >> 5;
    int lane = threadIdx.x & 31;
    if (w >= M) return;
    const float* ip = in + (long)w * HH;
    float x[8];
    float s = 0.f;
    #pragma unroll
    for (int i = 0; i < 8; i++) { x[i] = ip[lane + 32 * i]; s += x[i]; }
    s = warp_sum(s);
    float m = s * (1.f / 256.f);
    float q = 0.f;
    #pragma unroll
    for (int i = 0; i < 8; i++) { float d = x[i] - m; q += d * d; }
    q = warp_sum(q);
    float rs = rsqrtf(q * (1.f / 256.f) + 1e-5f);
    float* op = out + (long)w * HH;
    #pragma unroll
    for (int i = 0; i < 8; i++) {
        int c = lane + 32 * i;
        op[c] = (x[i] - m) * rs * g[c] + b[c];
    }
}

// ---------------- gather: Hsum[n] = sum_e h[src_e]  (warp per node, float4) ----------------
__global__ void gather_kernel() {
    int w = (blockIdx.x * 256 + threadIdx.x) >> 5;
    int lane = threadIdx.x & 31;
    if (w >= NN) return;
    float4 a0 = make_float4(0.f, 0.f, 0.f, 0.f);
    float4 a1 = make_float4(0.f, 0.f, 0.f, 0.f);
    int beg = g_rowptr[w], end = g_rowptr[w + 1];
    for (int e = beg; e < end; e++) {
        int s = g_csrc[e];
        const float4* hp = (const float4*)(g_h + (long)s * HH);
        float4 v0 = hp[lane];
        float4 v1 = hp[lane + 32];
        a0.x += v0.x; a0.y += v0.y; a0.z += v0.z; a0.w += v0.w;
        a1.x += v1.x; a1.y += v1.y; a1.z += v1.z; a1.w += v1.w;
    }
    float4* ap = (float4*)(g_Abuf + (long)w * KPAD);
    ap[lane] = a0;
    ap[lane + 32] = a1;
}

// ---------------- post-conv: h = LN(h + LN(silu(agg))) (warp per row) ----------------
__global__ void postconv_kernel(const float* __restrict__ cg, const float* __restrict__ cb,
                                const float* __restrict__ lg, const float* __restrict__ lb) {
    int w = (blockIdx.x * 256 + threadIdx.x) >> 5;
    int lane = threadIdx.x & 31;
    if (w >= NN) return;
    const float* ap = g_agg + (long)w * HH;
    float* hp = g_h + (long)w * HH;
    float x[8];
    float s = 0.f;
    #pragma unroll
    for (int i = 0; i < 8; i++) {
        float a = ap[lane + 32 * i];
        float v = silu_f(a);
        x[i] = v; s += v;
    }
    s = warp_sum(s);
    float m1 = s * (1.f / 256.f);
    float q = 0.f;
    #pragma unroll
    for (int i = 0; i < 8; i++) { float d = x[i] - m1; q += d * d; }
    q = warp_sum(q);
    float rs1 = rsqrtf(q * (1.f / 256.f) + 1e-5f);
    float z[8];
    float s2 = 0.f;
    #pragma unroll
    for (int i = 0; i < 8; i++) {
        int c = lane + 32 * i;
        float y = (x[i] - m1) * rs1 * cg[c] + cb[c];
        float zz = hp[c] + y;
        z[i] = zz; s2 += zz;
    }
    s2 = warp_sum(s2);
    float m2 = s2 * (1.f / 256.f);
    float q2 = 0.f;
    #pragma unroll
    for (int i = 0; i < 8; i++) { float d = z[i] - m2; q2 += d * d; }
    q2 = warp_sum(q2);
    float rs2 = rsqrtf(q2 * (1.f / 256.f) + 1e-5f);
    #pragma unroll
    for (int i = 0; i < 8; i++) {
        int c = lane + 32 * i;
        hp[c] = (z[i] - m2) * rs2 * lg[c] + lb[c];
    }
}

// ---------------- pooling ----------------
__global__ void gate_kernel(const float* __restrict__ pgW2, const float* __restrict__ pgb2) {
    int w = (blockIdx.x * 256 + threadIdx.x) >> 5;
    int lane = threadIdx.x & 31;
    if (w >= NN) return;
    float v = g_gatev[(long)w * 64 + lane] * pgW2[lane]
            + g_gatev[(long)w * 64 + 32 + lane] * pgW2[32 + lane];
    v = warp_sum(v);
    if (lane == 0) g_gate[w] = v + pgb2[0];
}

__global__ void maxpart_kernel() {
    __shared__ float sm[256];
    int tid = threadIdx.x;
    float m = -1e30f;
    for (int i = blockIdx.x * 256 + tid; i < NN; i += gridDim.x * 256)
        m = fmaxf(m, g_gate[i]);
    sm[tid] = m;
    __syncthreads();
    for (int o = 128; o; o >>= 1) {
        if (tid < o) sm[tid] = fmaxf(sm[tid], sm[tid + o]);
        __syncthreads();
    }
    if (tid == 0) g_partial[blockIdx.x] = sm[0];
}

__global__ void maxfin_kernel(int nb) {
    __shared__ float sm[256];
    int tid = threadIdx.x;
    sm[tid] = (tid < nb) ? g_partial[tid] : -1e30f;
    __syncthreads();
    for (int o = 128; o; o >>= 1) {
        if (tid < o) sm[tid] = fmaxf(sm[tid], sm[tid + o]);
        __syncthreads();
    }
    if (tid == 0) g_scal[0] = sm[0];
}

__global__ void expsum_kernel() {
    __shared__ float sm[256];
    int tid = threadIdx.x;
    int i = blockIdx.x * 256 + tid;
    float M = g_scal[0];
    float e = 0.f;
    if (i < NN) { e = expf(g_gate[i] - M); g_e[i] = e; }
    sm[tid] = e;
    __syncthreads();
    for (int o = 128; o; o >>= 1) {
        if (tid < o) sm[tid] += sm[tid + o];
        __syncthreads();
    }
    if (tid == 0) atomicAdd(&g_scal[1], sm[0]);
}

__global__ void wsum_kernel() {
    int t = threadIdx.x;
    int n0 = blockIdx.x * 256;
    float acc = 0.f;
    for (int i = 0; i < 256; i++) {
        int n = n0 + i;
        if (n >= NN) break;
        acc += g_e[n] * g_h[(long)n * HH + t];
    }
    atomicAdd(&g_Gvec[t], acc);
}

// ---------------- heads (single block) ----------------
__global__ void heads_kernel(const float* __restrict__ clW1, const float* __restrict__ clb1,
                             const float* __restrict__ clW2, const float* __restrict__ clb2,
                             const float* __restrict__ prW1, const float* __restrict__ prb1,
                             const float* __restrict__ prW2, const float* __restrict__ prb2,
                             float* __restrict__ out) {
    __shared__ float emb[256], c1[128], p1[256], pr[128];
    __shared__ float nrm;
    int t = threadIdx.x;
    float se = g_scal[1];
    float ev = g_Gvec[t] / se;
    emb[t] = ev;
    out[132 + t] = ev;   // graph_emb at [132..388)
    __syncthreads();
    if (t < 128) {
        float a = 0.f;
        for (int k = 0; k < 256; k++) a += emb[k] * clW1[k * 128 + t];
        a += clb1[t];
        c1[t] = silu_f(a);
    }
    {
        float a = 0.f;
        for (int k = 0; k < 256; k++) a += emb[k] * prW1[k * 256 + t];
        a += prb1[t];
        p1[t] = silu_f(a);
    }
    __syncthreads();
    if (t < 4) {
        float a = 0.f;
        for (int k = 0; k < 128; k++) a += c1[k] * clW2[k * 4 + t];
        out[t] = a + clb2[t];            // logits at [0..4)
    }
    if (t < 128) {
        float a = 0.f;
        for (int k = 0; k < 256; k++) a += p1[k] * prW2[k * 128 + t];
        pr[t] = a + prb2[t];
    }
    __syncthreads();
    if (t == 0) {
        float s = 0.f;
        for (int k = 0; k < 128; k++) s += pr[k] * pr[k];
        nrm = fmaxf(sqrtf(s), 1e-12f);
    }
    __syncthreads();
    if (t < 128) out[4 + t] = pr[t] / nrm;  // proj at [4..132)
}

// ---------------- launch ----------------
extern "C" void kernel_launch(void* const* d_in, const int* in_sizes, int n_in,
                              void* d_out, int out_size) {
    const float* x       = (const float*)d_in[0];
    const float* pos     = (const float*)d_in[1];
    const int*   ei      = (const int*)d_in[2];
    const float* ne_W1   = (const float*)d_in[3];
    const float* ne_b1   = (const float*)d_in[4];
    const float* ne_W2   = (const float*)d_in[5];
    const float* ne_b2   = (const float*)d_in[6];
    const float* ne_g    = (const float*)d_in[7];
    const float* ne_beta = (const float*)d_in[8];
    const float* convW   = (const float*)d_in[9];
    const float* convB   = (const float*)d_in[10];
    const float* convG   = (const float*)d_in[11];
    const float* convBeta= (const float*)d_in[12];
    const float* lnG     = (const float*)d_in[13];
    const float* lnB     = (const float*)d_in[14];
    const float* pgW1    = (const float*)d_in[15];
    const float* pgb1    = (const float*)d_in[16];
    const float* pgW2    = (const float*)d_in[17];
    const float* pgb2    = (const float*)d_in[18];
    const float* clW1    = (const float*)d_in[19];
    const float* clb1    = (const float*)d_in[20];
    const float* clW2    = (const float*)d_in[21];
    const float* clb2    = (const float*)d_in[22];
    const float* prW1    = (const float*)d_in[23];
    const float* prb1    = (const float*)d_in[24];
    const float* prW2    = (const float*)d_in[25];
    const float* prb2    = (const float*)d_in[26];
    float* out = (float*)d_out;

    float *p_t1, *p_h, *p_Abuf, *p_agg, *p_gatev, *p_Wpack;
    cudaGetSymbolAddress((void**)&p_t1, g_t1);
    cudaGetSymbolAddress((void**)&p_h, g_h);
    cudaGetSymbolAddress((void**)&p_Abuf, g_Abuf);
    cudaGetSymbolAddress((void**)&p_agg, g_agg);
    cudaGetSymbolAddress((void**)&p_gatev, g_gatev);
    cudaGetSymbolAddress((void**)&p_Wpack, g_Wpack);

    const int EB = (EE + 255) / 256;
    const int NB = (NN + 255) / 256;
    const int WB = (NN + 7) / 8;          // warp-per-row blocks (256 thr = 8 warps)
    const int MB = (NN + 127) / 128;      // 391

    // setup (edges/pos layer-invariant)
    zero_kernel<<<NB, 256>>>();
    edge1_kernel<<<EB, 256>>>(ei);
    scan_kernel<<<1, 1024>>>();
    edge2_kernel<<<EB, 256>>>(ei);
    ef_kernel<<<NB, 256>>>(pos);
    pack_kernel<<<(LL * KPAD * HH + 255) / 256, 256>>>(convW, convB);

    // node encoder
    mma_gemm_kernel<<<dim3(MB, 2), 256>>>(x, NIN, ne_W1, HH, ne_b1, p_t1, HH, NN, HH, NIN, 1);
    mma_gemm_kernel<<<dim3(MB, 2), 256>>>(p_t1, HH, ne_W2, HH, ne_b2, p_agg, HH, NN, HH, HH, 0);
    ln_kernel<<<WB, 256>>>(p_agg, ne_g, ne_beta, p_h, NN);

    // conv layers
    for (int l = 0; l < LL; l++) {
        gather_kernel<<<WB, 256>>>();
        mma_gemm_kernel<<<dim3(MB, 2), 256>>>(p_Abuf, KPAD, p_Wpack + (long)l * KPAD * HH, HH,
                                              nullptr, p_agg, HH, NN, HH, KPAD, 0);
        postconv_kernel<<<WB, 256>>>(convG + l * HH, convBeta + l * HH,
                                     lnG + l * HH, lnB + l * HH);
    }

    // attention pooling
    mma_gemm_kernel<<<dim3(MB, 1), 256>>>(p_h, HH, pgW1, 64, pgb1, p_gatev, 64, NN, 64, HH, 1);
    gate_kernel<<<WB, 256>>>(pgW2, pgb2);
    maxpart_kernel<<<64, 256>>>();
    maxfin_kernel<<<1, 256>>>(64);
    expsum_kernel<<<NB, 256>>>();
    wsum_kernel<<<NB, 256>>>();

    // heads
    heads_kernel<<<1, 256>>>(clW1, clb1, clW2, clb2, prW1, prb1, prW2, prb2, out);
}

// round 4
// speedup vs baseline: 1.9092x; 1.1461x over previous
#include <cuda_runtime.h>
#include <math.h>

#define NN 50000
#define EE 1000000
#define NIN 1281
#define HH 256
#define LL 4
#define KPAD 288   // 256 Hsum + 3 sh + 16 radial + 1 deg + 12 zero pad

// ---------------- scratch (device globals; no runtime allocation) ----------------
__device__ float g_t1[NN * HH];
__device__ float g_h[NN * HH];
__device__ float g_Abuf[NN * KPAD];
__device__ float g_agg[NN * HH];
__device__ float g_gatev[NN * 64];
__device__ float g_gate[NN];
__device__ float g_e[NN];
__device__ int   g_deg[NN];
__device__ int   g_rowptr[NN + 1];
__device__ int   g_cursor[NN];
__device__ int   g_csrc[EE];
__device__ float g_Wpack[LL * KPAD * HH];
__device__ float g_partial[256];
__device__ float g_scal[4];
__device__ float g_Gvec[HH];
__device__ int   g_bsum[64];

// ---------------- helpers ----------------
__device__ __forceinline__ float warp_sum(float v) {
    #pragma unroll
    for (int o = 16; o; o >>= 1) v += __shfl_xor_sync(0xffffffffu, v, o);
    return v;
}
__device__ __forceinline__ float silu_f(float x) { return x / (1.f + expf(-x)); }
__device__ __forceinline__ unsigned f2tf(float f) {
    unsigned r;
    asm("cvt.rna.tf32.f32 %0, %1;" : "=r"(r) : "f"(f));
    return r;
}

// ---------------- setup kernels ----------------
__global__ void zero_kernel() {
    int i = blockIdx.x * 256 + threadIdx.x;
    if (i < NN) { g_deg[i] = 0; g_cursor[i] = 0; }
    if (i < HH) g_Gvec[i] = 0.f;
    if (i < 4) g_scal[i] = 0.f;
    if (i == 0) g_rowptr[0] = 0;
}

__global__ void edge1_kernel(const int* __restrict__ ei) {
    int e = blockIdx.x * 256 + threadIdx.x;
    if (e >= EE) return;
    atomicAdd(&g_deg[ei[EE + e]], 1);
}

// multi-block scan: stage 1 (block-local inclusive scan)
__global__ void scan1_kernel() {
    __shared__ int s[1024];
    int tid = threadIdx.x;
    int gid = blockIdx.x * 1024 + tid;
    int v = (gid < NN) ? g_deg[gid] : 0;
    s[tid] = v;
    __syncthreads();
    for (int off = 1; off < 1024; off <<= 1) {
        int t = (tid >= off) ? s[tid - off] : 0;
        __syncthreads();
        s[tid] += t;
        __syncthreads();
    }
    if (gid < NN) g_rowptr[gid + 1] = s[tid];
    if (tid == 1023) g_bsum[blockIdx.x] = s[1023];
}

// stage 2: scan block sums (49 values)
__global__ void scan2_kernel(int nb) {
    __shared__ int s[64];
    int tid = threadIdx.x;
    s[tid] = (tid < nb) ? g_bsum[tid] : 0;
    __syncthreads();
    for (int off = 1; off < 64; off <<= 1) {
        int t = (tid >= off) ? s[tid - off] : 0;
        __syncthreads();
        s[tid] += t;
        __syncthreads();
    }
    if (tid < nb) g_bsum[tid] = s[tid];
}

// stage 3: add block offsets
__global__ void scan3_kernel() {
    int gid = blockIdx.x * 256 + threadIdx.x;
    if (gid >= NN) return;
    int b = gid >> 10;
    if (b > 0) g_rowptr[gid + 1] += g_bsum[b - 1];
}

__global__ void edge2_kernel(const int* __restrict__ ei) {
    int e = blockIdx.x * 256 + threadIdx.x;
    if (e >= EE) return;
    int s = ei[e];
    int d = ei[EE + e];
    int slot = atomicAdd(&g_cursor[d], 1);
    g_csrc[g_rowptr[d] + slot] = s;
}

// per-node edge-feature aggregation with 2-exp factorization fast path
__global__ void ef_kernel(const float* __restrict__ pos) {
    int n = blockIdx.x * 256 + threadIdx.x;
    if (n >= NN) return;
    const float w = 0.1953125f;           // 0.5*(10/16)^2
    const float cstep = 10.f / 15.f;
    float Ej[16];
    #pragma unroll
    for (int j = 0; j < 16; j++) {
        float c = cstep * (float)j;
        Ej[j] = expf(-w * c * c);
    }
    float px = pos[3 * n + 0], py = pos[3 * n + 1], pz = pos[3 * n + 2];
    float shx = 0.f, shy = 0.f, shz = 0.f;
    float rad[16];
    #pragma unroll
    for (int j = 0; j < 16; j++) rad[j] = 0.f;
    int beg = g_rowptr[n], end = g_rowptr[n + 1];
    for (int e = beg; e < end; e++) {
        int s = g_csrc[e];
        float rx = px - pos[3 * s + 0];
        float ry = py - pos[3 * s + 1];
        float rz = pz - pos[3 * s + 2];
        float dist = sqrtf(rx * rx + ry * ry + rz * rz);
        float inv = 1.f / fmaxf(dist, 1e-12f);
        shx += rx * inv; shy += ry * inv; shz += rz * inv;
        if (dist < 18.f) {
            float A = expf(-w * dist * dist);
            float r = expf(2.f * w * cstep * dist);
            float p = A;
            #pragma unroll
            for (int j = 0; j < 16; j++) {
                rad[j] += p * Ej[j];
                p *= r;
            }
        } else {
            #pragma unroll
            for (int j = 0; j < 16; j++) {
                float t = dist - cstep * (float)j;
                rad[j] += expf(-w * t * t);
            }
        }
    }
    float* ab = g_Abuf + (long)n * KPAD + 256;
    ab[0] = shx; ab[1] = shy; ab[2] = shz;
    #pragma unroll
    for (int j = 0; j < 16; j++) ab[3 + j] = rad[j];
    ab[19] = (float)(end - beg);
    #pragma unroll
    for (int j = 20; j < 32; j++) ab[j] = 0.f;
}

__global__ void pack_kernel(const float* __restrict__ convW, const float* __restrict__ convB) {
    int idx = blockIdx.x * 256 + threadIdx.x;
    const int total = LL * KPAD * HH;
    if (idx >= total) return;
    int l = idx / (KPAD * HH);
    int r = (idx / HH) % KPAD;
    int c = idx % HH;
    float v = 0.f;
    if (r < 275)      v = convW[((long)l * 275 + r) * HH + c];
    else if (r == 275) v = convB[l * HH + c];
    g_Wpack[idx] = v;
}

// ---------------- TF32 MMA GEMM, double-buffered: C = act(A@B + bias) ----------------
// BM=128, BN=128, BK=16; 8 warps (2x4); warp tile 64x32; mma m16n8k8 tf32
#define ASTRIDE 20
#define BSTRIDE 136
__global__ __launch_bounds__(256, 2)
void mma_gemm_kernel(const float* __restrict__ A, int lda,
                     const float* __restrict__ B, int ldb,
                     const float* __restrict__ bias,
                     float* __restrict__ C, int ldc,
                     int M, int Ncols, int K, int act) {
    __shared__ unsigned As[2][128 * ASTRIDE];
    __shared__ unsigned Bs[2][16 * BSTRIDE];
    int t = threadIdx.x;
    int lane = t & 31, warp = t >> 5;
    int wr = warp >> 2;
    int wc = warp & 3;
    int rowBase = blockIdx.x * 128;
    int colBase = blockIdx.y * 128;

    float acc[4][4][4];
    #pragma unroll
    for (int mi = 0; mi < 4; mi++)
        #pragma unroll
        for (int ni = 0; ni < 4; ni++)
            #pragma unroll
            for (int q = 0; q < 4; q++) acc[mi][ni][q] = 0.f;

    // load mappings
    int aRow = t >> 1;            // 0..127
    int aK0 = (t & 1) * 8;        // 0 or 8
    int bK = t >> 4;              // 0..15
    int bN0 = (t & 15) * 8;       // 0..120

    int gr = rowBase + aRow;
    const float* Arow = A + (long)gr * lda;
    int numT = (K + 15) / 16;

    float aF[8];
    float bF[8];

    // prologue: load tile 0
    {
        #pragma unroll
        for (int v = 0; v < 8; v++) {
            int gk = aK0 + v;
            aF[v] = (gr < M && gk < K) ? Arow[gk] : 0.f;
        }
        int gk = bK;
        int gc = colBase + bN0;
        #pragma unroll
        for (int h = 0; h < 2; h++) {
            float4 d = make_float4(0.f, 0.f, 0.f, 0.f);
            if (gk < K && gc + h * 4 < Ncols)
                d = *(const float4*)(B + (long)gk * ldb + gc + h * 4);
            bF[h * 4 + 0] = d.x; bF[h * 4 + 1] = d.y;
            bF[h * 4 + 2] = d.z; bF[h * 4 + 3] = d.w;
        }
        unsigned* as = &As[0][aRow * ASTRIDE + aK0];
        #pragma unroll
        for (int v = 0; v < 8; v++) as[v] = f2tf(aF[v]);
        unsigned* bs = &Bs[0][bK * BSTRIDE + bN0];
        #pragma unroll
        for (int v = 0; v < 8; v++) bs[v] = f2tf(bF[v]);
    }
    __syncthreads();

    for (int ti = 0; ti < numT; ti++) {
        int cur = ti & 1;
        // prefetch tile ti+1 into registers
        if (ti + 1 < numT) {
            int k0 = (ti + 1) * 16;
            #pragma unroll
            for (int v = 0; v < 8; v++) {
                int gk = k0 + aK0 + v;
                aF[v] = (gr < M && gk < K) ? Arow[gk] : 0.f;
            }
            int gk = k0 + bK;
            int gc = colBase + bN0;
            #pragma unroll
            for (int h = 0; h < 2; h++) {
                float4 d = make_float4(0.f, 0.f, 0.f, 0.f);
                if (gk < K && gc + h * 4 < Ncols)
                    d = *(const float4*)(B + (long)gk * ldb + gc + h * 4);
                bF[h * 4 + 0] = d.x; bF[h * 4 + 1] = d.y;
                bF[h * 4 + 2] = d.z; bF[h * 4 + 3] = d.w;
            }
        }
        // MMA over current buffer
        const unsigned* as = As[cur];
        const unsigned* bs = Bs[cur];
        #pragma unroll
        for (int kk = 0; kk < 2; kk++) {
            int ko = kk * 8;
            unsigned af[4][4], bf[4][2];
            #pragma unroll
            for (int mi = 0; mi < 4; mi++) {
                int ar = wr * 64 + mi * 16 + (lane >> 2);
                af[mi][0] = as[ar * ASTRIDE + ko + (lane & 3)];
                af[mi][1] = as[(ar + 8) * ASTRIDE + ko + (lane & 3)];
                af[mi][2] = as[ar * ASTRIDE + ko + (lane & 3) + 4];
                af[mi][3] = as[(ar + 8) * ASTRIDE + ko + (lane & 3) + 4];
            }
            #pragma unroll
            for (int ni = 0; ni < 4; ni++) {
                int bn = wc * 32 + ni * 8 + (lane >> 2);
                bf[ni][0] = bs[(ko + (lane & 3)) * BSTRIDE + bn];
                bf[ni][1] = bs[(ko + (lane & 3) + 4) * BSTRIDE + bn];
            }
            #pragma unroll
            for (int mi = 0; mi < 4; mi++)
                #pragma unroll
                for (int ni = 0; ni < 4; ni++) {
                    asm volatile(
                        "mma.sync.aligned.m16n8k8.row.col.f32.tf32.tf32.f32 "
                        "{%0,%1,%2,%3}, {%4,%5,%6,%7}, {%8,%9}, {%0,%1,%2,%3};"
                        : "+f"(acc[mi][ni][0]), "+f"(acc[mi][ni][1]),
                          "+f"(acc[mi][ni][2]), "+f"(acc[mi][ni][3])
                        : "r"(af[mi][0]), "r"(af[mi][1]), "r"(af[mi][2]), "r"(af[mi][3]),
                          "r"(bf[ni][0]), "r"(bf[ni][1]));
                }
        }
        // store prefetched tile into other buffer
        if (ti + 1 < numT) {
            int nxt = (ti + 1) & 1;
            unsigned* asw = &As[nxt][aRow * ASTRIDE + aK0];
            #pragma unroll
            for (int v = 0; v < 8; v++) asw[v] = f2tf(aF[v]);
            unsigned* bsw = &Bs[nxt][bK * BSTRIDE + bN0];
            #pragma unroll
            for (int v = 0; v < 8; v++) bsw[v] = f2tf(bF[v]);
        }
        __syncthreads();
    }

    // epilogue
    #pragma unroll
    for (int mi = 0; mi < 4; mi++) {
        #pragma unroll
        for (int ni = 0; ni < 4; ni++) {
            int r0 = rowBase + wr * 64 + mi * 16 + (lane >> 2);
            int c0 = colBase + wc * 32 + ni * 8 + (lane & 3) * 2;
            #pragma unroll
            for (int half = 0; half < 2; half++) {
                int r = r0 + half * 8;
                if (r >= M) continue;
                #pragma unroll
                for (int q = 0; q < 2; q++) {
                    int c = c0 + q;
                    if (c >= Ncols) continue;
                    float v = acc[mi][ni][half * 2 + q] + (bias ? bias[c] : 0.f);
                    if (act) v = silu_f(v);
                    C[(long)r * ldc + c] = v;
                }
            }
        }
    }
}

// ---------------- LayerNorm (warp per row of 256) ----------------
__global__ void ln_kernel(const float* __restrict__ in, const float* __restrict__ g,
                          const float* __restrict__ b, float* __restrict__ out, int M) {
    int w = (blockIdx.x * blockDim.x + threadIdx.x) >> 5;
    int lane = threadIdx.x & 31;
    if (w >= M) return;
    const float* ip = in + (long)w * HH;
    float x[8];
    float s = 0.f;
    #pragma unroll
    for (int i = 0; i < 8; i++) { x[i] = ip[lane + 32 * i]; s += x[i]; }
    s = warp_sum(s);
    float m = s * (1.f / 256.f);
    float q = 0.f;
    #pragma unroll
    for (int i = 0; i < 8; i++) { float d = x[i] - m; q += d * d; }
    q = warp_sum(q);
    float rs = rsqrtf(q * (1.f / 256.f) + 1e-5f);
    float* op = out + (long)w * HH;
    #pragma unroll
    for (int i = 0; i < 8; i++) {
        int c = lane + 32 * i;
        op[c] = (x[i] - m) * rs * g[c] + b[c];
    }
}

// ---------------- gather: Hsum[n] = sum_e h[src_e]  (warp per node, float4, 2x unroll) ----
__global__ void gather_kernel() {
    int w = (blockIdx.x * 256 + threadIdx.x) >> 5;
    int lane = threadIdx.x & 31;
    if (w >= NN) return;
    float4 a0 = make_float4(0.f, 0.f, 0.f, 0.f);
    float4 a1 = make_float4(0.f, 0.f, 0.f, 0.f);
    float4 c0 = make_float4(0.f, 0.f, 0.f, 0.f);
    float4 c1 = make_float4(0.f, 0.f, 0.f, 0.f);
    int beg = g_rowptr[w], end = g_rowptr[w + 1];
    int e = beg;
    for (; e + 1 < end; e += 2) {
        int s0 = g_csrc[e];
        int s1 = g_csrc[e + 1];
        const float4* h0 = (const float4*)(g_h + (long)s0 * HH);
        const float4* h1 = (const float4*)(g_h + (long)s1 * HH);
        float4 v0 = h0[lane];
        float4 v1 = h0[lane + 32];
        float4 u0 = h1[lane];
        float4 u1 = h1[lane + 32];
        a0.x += v0.x; a0.y += v0.y; a0.z += v0.z; a0.w += v0.w;
        a1.x += v1.x; a1.y += v1.y; a1.z += v1.z; a1.w += v1.w;
        c0.x += u0.x; c0.y += u0.y; c0.z += u0.z; c0.w += u0.w;
        c1.x += u1.x; c1.y += u1.y; c1.z += u1.z; c1.w += u1.w;
    }
    if (e < end) {
        int s0 = g_csrc[e];
        const float4* h0 = (const float4*)(g_h + (long)s0 * HH);
        float4 v0 = h0[lane];
        float4 v1 = h0[lane + 32];
        a0.x += v0.x; a0.y += v0.y; a0.z += v0.z; a0.w += v0.w;
        a1.x += v1.x; a1.y += v1.y; a1.z += v1.z; a1.w += v1.w;
    }
    a0.x += c0.x; a0.y += c0.y; a0.z += c0.z; a0.w += c0.w;
    a1.x += c1.x; a1.y += c1.y; a1.z += c1.z; a1.w += c1.w;
    float4* ap = (float4*)(g_Abuf + (long)w * KPAD);
    ap[lane] = a0;
    ap[lane + 32] = a1;
}

// ---------------- post-conv: h = LN(h + LN(silu(agg))) ----------------
__global__ void postconv_kernel(const float* __restrict__ cg, const float* __restrict__ cb,
                                const float* __restrict__ lg, const float* __restrict__ lb) {
    int w = (blockIdx.x * 256 + threadIdx.x) >> 5;
    int lane = threadIdx.x & 31;
    if (w >= NN) return;
    const float* ap = g_agg + (long)w * HH;
    float* hp = g_h + (long)w * HH;
    float x[8];
    float s = 0.f;
    #pragma unroll
    for (int i = 0; i < 8; i++) {
        float a = ap[lane + 32 * i];
        float v = silu_f(a);
        x[i] = v; s += v;
    }
    s = warp_sum(s);
    float m1 = s * (1.f / 256.f);
    float q = 0.f;
    #pragma unroll
    for (int i = 0; i < 8; i++) { float d = x[i] - m1; q += d * d; }
    q = warp_sum(q);
    float rs1 = rsqrtf(q * (1.f / 256.f) + 1e-5f);
    float z[8];
    float s2 = 0.f;
    #pragma unroll
    for (int i = 0; i < 8; i++) {
        int c = lane + 32 * i;
        float y = (x[i] - m1) * rs1 * cg[c] + cb[c];
        float zz = hp[c] + y;
        z[i] = zz; s2 += zz;
    }
    s2 = warp_sum(s2);
    float m2 = s2 * (1.f / 256.f);
    float q2 = 0.f;
    #pragma unroll
    for (int i = 0; i < 8; i++) { float d = z[i] - m2; q2 += d * d; }
    q2 = warp_sum(q2);
    float rs2 = rsqrtf(q2 * (1.f / 256.f) + 1e-5f);
    #pragma unroll
    for (int i = 0; i < 8; i++) {
        int c = lane + 32 * i;
        hp[c] = (z[i] - m2) * rs2 * lg[c] + lb[c];
    }
}

// ---------------- pooling ----------------
__global__ void gate_kernel(const float* __restrict__ pgW2, const float* __restrict__ pgb2) {
    int w = (blockIdx.x * 256 + threadIdx.x) >> 5;
    int lane = threadIdx.x & 31;
    if (w >= NN) return;
    float v = g_gatev[(long)w * 64 + lane] * pgW2[lane]
            + g_gatev[(long)w * 64 + 32 + lane] * pgW2[32 + lane];
    v = warp_sum(v);
    if (lane == 0) g_gate[w] = v + pgb2[0];
}

__global__ void maxpart_kernel() {
    __shared__ float sm[256];
    int tid = threadIdx.x;
    float m = -1e30f;
    for (int i = blockIdx.x * 256 + tid; i < NN; i += gridDim.x * 256)
        m = fmaxf(m, g_gate[i]);
    sm[tid] = m;
    __syncthreads();
    for (int o = 128; o; o >>= 1) {
        if (tid < o) sm[tid] = fmaxf(sm[tid], sm[tid + o]);
        __syncthreads();
    }
    if (tid == 0) g_partial[blockIdx.x] = sm[0];
}

__global__ void maxfin_kernel(int nb) {
    __shared__ float sm[256];
    int tid = threadIdx.x;
    sm[tid] = (tid < nb) ? g_partial[tid] : -1e30f;
    __syncthreads();
    for (int o = 128; o; o >>= 1) {
        if (tid < o) sm[tid] = fmaxf(sm[tid], sm[tid + o]);
        __syncthreads();
    }
    if (tid == 0) g_scal[0] = sm[0];
}

__global__ void expsum_kernel() {
    __shared__ float sm[256];
    int tid = threadIdx.x;
    int i = blockIdx.x * 256 + tid;
    float M = g_scal[0];
    float e = 0.f;
    if (i < NN) { e = expf(g_gate[i] - M); g_e[i] = e; }
    sm[tid] = e;
    __syncthreads();
    for (int o = 128; o; o >>= 1) {
        if (tid < o) sm[tid] += sm[tid + o];
        __syncthreads();
    }
    if (tid == 0) atomicAdd(&g_scal[1], sm[0]);
}

__global__ void wsum_kernel() {
    int t = threadIdx.x;
    int n0 = blockIdx.x * 256;
    float acc = 0.f;
    for (int i = 0; i < 256; i++) {
        int n = n0 + i;
        if (n >= NN) break;
        acc += g_e[n] * g_h[(long)n * HH + t];
    }
    atomicAdd(&g_Gvec[t], acc);
}

// ---------------- heads (single block) ----------------
__global__ void heads_kernel(const float* __restrict__ clW1, const float* __restrict__ clb1,
                             const float* __restrict__ clW2, const float* __restrict__ clb2,
                             const float* __restrict__ prW1, const float* __restrict__ prb1,
                             const float* __restrict__ prW2, const float* __restrict__ prb2,
                             float* __restrict__ out) {
    __shared__ float emb[256], c1[128], p1[256], pr[128];
    __shared__ float nrm;
    int t = threadIdx.x;
    float se = g_scal[1];
    float ev = g_Gvec[t] / se;
    emb[t] = ev;
    out[132 + t] = ev;
    __syncthreads();
    if (t < 128) {
        float a = 0.f;
        for (int k = 0; k < 256; k++) a += emb[k] * clW1[k * 128 + t];
        a += clb1[t];
        c1[t] = silu_f(a);
    }
    {
        float a = 0.f;
        for (int k = 0; k < 256; k++) a += emb[k] * prW1[k * 256 + t];
        a += prb1[t];
        p1[t] = silu_f(a);
    }
    __syncthreads();
    if (t < 4) {
        float a = 0.f;
        for (int k = 0; k < 128; k++) a += c1[k] * clW2[k * 4 + t];
        out[t] = a + clb2[t];
    }
    if (t < 128) {
        float a = 0.f;
        for (int k = 0; k < 256; k++) a += p1[k] * prW2[k * 128 + t];
        pr[t] = a + prb2[t];
    }
    __syncthreads();
    if (t == 0) {
        float s = 0.f;
        for (int k = 0; k < 128; k++) s += pr[k] * pr[k];
        nrm = fmaxf(sqrtf(s), 1e-12f);
    }
    __syncthreads();
    if (t < 128) out[4 + t] = pr[t] / nrm;
}

// ---------------- launch ----------------
extern "C" void kernel_launch(void* const* d_in, const int* in_sizes, int n_in,
                              void* d_out, int out_size) {
    const float* x       = (const float*)d_in[0];
    const float* pos     = (const float*)d_in[1];
    const int*   ei      = (const int*)d_in[2];
    const float* ne_W1   = (const float*)d_in[3];
    const float* ne_b1   = (const float*)d_in[4];
    const float* ne_W2   = (const float*)d_in[5];
    const float* ne_b2   = (const float*)d_in[6];
    const float* ne_g    = (const float*)d_in[7];
    const float* ne_beta = (const float*)d_in[8];
    const float* convW   = (const float*)d_in[9];
    const float* convB   = (const float*)d_in[10];
    const float* convG   = (const float*)d_in[11];
    const float* convBeta= (const float*)d_in[12];
    const float* lnG     = (const float*)d_in[13];
    const float* lnB     = (const float*)d_in[14];
    const float* pgW1    = (const float*)d_in[15];
    const float* pgb1    = (const float*)d_in[16];
    const float* pgW2    = (const float*)d_in[17];
    const float* pgb2    = (const float*)d_in[18];
    const float* clW1    = (const float*)d_in[19];
    const float* clb1    = (const float*)d_in[20];
    const float* clW2    = (const float*)d_in[21];
    const float* clb2    = (const float*)d_in[22];
    const float* prW1    = (const float*)d_in[23];
    const float* prb1    = (const float*)d_in[24];
    const float* prW2    = (const float*)d_in[25];
    const float* prb2    = (const float*)d_in[26];
    float* out = (float*)d_out;

    float *p_t1, *p_h, *p_Abuf, *p_agg, *p_gatev, *p_Wpack;
    cudaGetSymbolAddress((void**)&p_t1, g_t1);
    cudaGetSymbolAddress((void**)&p_h, g_h);
    cudaGetSymbolAddress((void**)&p_Abuf, g_Abuf);
    cudaGetSymbolAddress((void**)&p_agg, g_agg);
    cudaGetSymbolAddress((void**)&p_gatev, g_gatev);
    cudaGetSymbolAddress((void**)&p_Wpack, g_Wpack);

    const int EB = (EE + 255) / 256;
    const int NB = (NN + 255) / 256;
    const int WB = (NN + 7) / 8;
    const int MB = (NN + 127) / 128;
    const int SB = (NN + 1023) / 1024;   // 49 scan blocks

    // setup
    zero_kernel<<<NB, 256>>>();
    edge1_kernel<<<EB, 256>>>(ei);
    scan1_kernel<<<SB, 1024>>>();
    scan2_kernel<<<1, 64>>>(SB);
    scan3_kernel<<<NB, 256>>>();
    edge2_kernel<<<EB, 256>>>(ei);
    ef_kernel<<<NB, 256>>>(pos);
    pack_kernel<<<(LL * KPAD * HH + 255) / 256, 256>>>(convW, convB);

    // node encoder
    mma_gemm_kernel<<<dim3(MB, 2), 256>>>(x, NIN, ne_W1, HH, ne_b1, p_t1, HH, NN, HH, NIN, 1);
    mma_gemm_kernel<<<dim3(MB, 2), 256>>>(p_t1, HH, ne_W2, HH, ne_b2, p_agg, HH, NN, HH, HH, 0);
    ln_kernel<<<WB, 256>>>(p_agg, ne_g, ne_beta, p_h, NN);

    // conv layers
    for (int l = 0; l < LL; l++) {
        gather_kernel<<<WB, 256>>>();
        mma_gemm_kernel<<<dim3(MB, 2), 256>>>(p_Abuf, KPAD, p_Wpack + (long)l * KPAD * HH, HH,
                                              nullptr, p_agg, HH, NN, HH, KPAD, 0);
        postconv_kernel<<<WB, 256>>>(convG + l * HH, convBeta + l * HH,
                                     lnG + l * HH, lnB + l * HH);
    }

    // attention pooling
    mma_gemm_kernel<<<dim3(MB, 1), 256>>>(p_h, HH, pgW1, 64, pgb1, p_gatev, 64, NN, 64, HH, 1);
    gate_kernel<<<WB, 256>>>(pgW2, pgb2);
    maxpart_kernel<<<64, 256>>>();
    maxfin_kernel<<<1, 256>>>(64);
    expsum_kernel<<<NB, 256>>>();
    wsum_kernel<<<NB, 256>>>();

    // heads
    heads_kernel<<<1, 256>>>(clW1, clb1, clW2, clb2, prW1, prb1, prW2, prb2, out);
}

// round 6
// speedup vs baseline: 2.0822x; 1.0907x over previous
#include <cuda_runtime.h>
#include <math.h>
#include <stdint.h>

#define NN 50000
#define EE 1000000
#define NIN 1281
#define K1PAD 1312          // 1281 padded to multiple of 32
#define HH 256
#define LL 4
#define KPAD 288            // 256 Hsum + 3 sh + 16 radial + 1 deg + 12 zero pad

// ---------------- scratch (device globals; no runtime allocation) ----------------
__device__ float g_xr[NN * K1PAD];         // tf32-rounded, padded x; later reused for rounded h
__device__ float g_t1[NN * HH];
__device__ float g_h[NN * HH];
__device__ float g_Abuf[NN * KPAD];
__device__ float g_agg[NN * HH];
__device__ float g_gatev[NN * 64];
__device__ float g_gate[NN];
__device__ float g_e[NN];
__device__ int   g_deg[NN];
__device__ int   g_rowptr[NN + 1];
__device__ int   g_cursor[NN];
__device__ int   g_csrc[EE];
__device__ float g_W1t[HH * K1PAD];        // ne_W1 transposed [256][1312], tf32-rounded
__device__ float g_W2t[HH * HH];
__device__ float g_pgW1t[64 * HH];
__device__ float g_WpackT[LL * HH * KPAD];
__device__ float g_partial[256];
__device__ float g_scal[4];
__device__ float g_Gvec[HH];
__device__ int   g_bsum[64];

// ---------------- helpers ----------------
__device__ __forceinline__ float warp_sum(float v) {
    #pragma unroll
    for (int o = 16; o; o >>= 1) v += __shfl_xor_sync(0xffffffffu, v, o);
    return v;
}
__device__ __forceinline__ float silu_f(float x) { return x / (1.f + expf(-x)); }
__device__ __forceinline__ unsigned f2tf(float f) {
    unsigned r;
    asm("cvt.rna.tf32.f32 %0, %1;" : "=r"(r) : "f"(f));
    return r;
}
__device__ __forceinline__ float f2tff(float f) { return __uint_as_float(f2tf(f)); }
__device__ __forceinline__ uint32_t smem_u32(const void* p) {
    uint32_t a;
    asm("{ .reg .u64 t; cvta.to.shared.u64 t, %1; cvt.u32.u64 %0, t; }" : "=r"(a) : "l"(p));
    return a;
}
#define CP_ASYNC16(dst, src) \
    asm volatile("cp.async.ca.shared.global [%0], [%1], 16;" :: "r"(dst), "l"(src))
#define CP_COMMIT() asm volatile("cp.async.commit_group;" ::: "memory")
#define CP_WAIT2()  asm volatile("cp.async.wait_group 2;" ::: "memory")

// ---------------- setup kernels ----------------
__global__ void zero_kernel() {
    int i = blockIdx.x * 256 + threadIdx.x;
    if (i < NN) { g_deg[i] = 0; g_cursor[i] = 0; }
    if (i < HH) g_Gvec[i] = 0.f;
    if (i < 4) g_scal[i] = 0.f;
    if (i == 0) g_rowptr[0] = 0;
}

__global__ void edge1_kernel(const int* __restrict__ ei) {
    int e = blockIdx.x * 256 + threadIdx.x;
    if (e >= EE) return;
    atomicAdd(&g_deg[ei[EE + e]], 1);
}

__global__ void scan1_kernel() {
    __shared__ int s[1024];
    int tid = threadIdx.x;
    int gid = blockIdx.x * 1024 + tid;
    int v = (gid < NN) ? g_deg[gid] : 0;
    s[tid] = v;
    __syncthreads();
    for (int off = 1; off < 1024; off <<= 1) {
        int t = (tid >= off) ? s[tid - off] : 0;
        __syncthreads();
        s[tid] += t;
        __syncthreads();
    }
    if (gid < NN) g_rowptr[gid + 1] = s[tid];
    if (tid == 1023) g_bsum[blockIdx.x] = s[1023];
}

__global__ void scan2_kernel(int nb) {
    __shared__ int s[64];
    int tid = threadIdx.x;
    s[tid] = (tid < nb) ? g_bsum[tid] : 0;
    __syncthreads();
    for (int off = 1; off < 64; off <<= 1) {
        int t = (tid >= off) ? s[tid - off] : 0;
        __syncthreads();
        s[tid] += t;
        __syncthreads();
    }
    if (tid < nb) g_bsum[tid] = s[tid];
}

__global__ void scan3_kernel() {
    int gid = blockIdx.x * 256 + threadIdx.x;
    if (gid >= NN) return;
    int b = gid >> 10;
    if (b > 0) g_rowptr[gid + 1] += g_bsum[b - 1];
}

__global__ void edge2_kernel(const int* __restrict__ ei) {
    int e = blockIdx.x * 256 + threadIdx.x;
    if (e >= EE) return;
    int s = ei[e];
    int d = ei[EE + e];
    int slot = atomicAdd(&g_cursor[d], 1);
    g_csrc[g_rowptr[d] + slot] = s;
}

__global__ void ef_kernel(const float* __restrict__ pos) {
    int n = blockIdx.x * 256 + threadIdx.x;
    if (n >= NN) return;
    const float w = 0.1953125f;
    const float cstep = 10.f / 15.f;
    float Ej[16];
    #pragma unroll
    for (int j = 0; j < 16; j++) {
        float c = cstep * (float)j;
        Ej[j] = expf(-w * c * c);
    }
    float px = pos[3 * n + 0], py = pos[3 * n + 1], pz = pos[3 * n + 2];
    float shx = 0.f, shy = 0.f, shz = 0.f;
    float rad[16];
    #pragma unroll
    for (int j = 0; j < 16; j++) rad[j] = 0.f;
    int beg = g_rowptr[n], end = g_rowptr[n + 1];
    for (int e = beg; e < end; e++) {
        int s = g_csrc[e];
        float rx = px - pos[3 * s + 0];
        float ry = py - pos[3 * s + 1];
        float rz = pz - pos[3 * s + 2];
        float dist = sqrtf(rx * rx + ry * ry + rz * rz);
        float inv = 1.f / fmaxf(dist, 1e-12f);
        shx += rx * inv; shy += ry * inv; shz += rz * inv;
        if (dist < 18.f) {
            float A = expf(-w * dist * dist);
            float r = expf(2.f * w * cstep * dist);
            float p = A;
            #pragma unroll
            for (int j = 0; j < 16; j++) {
                rad[j] += p * Ej[j];
                p *= r;
            }
        } else {
            #pragma unroll
            for (int j = 0; j < 16; j++) {
                float t = dist - cstep * (float)j;
                rad[j] += expf(-w * t * t);
            }
        }
    }
    float* ab = g_Abuf + (long)n * KPAD + 256;
    ab[0] = f2tff(shx); ab[1] = f2tff(shy); ab[2] = f2tff(shz);
    #pragma unroll
    for (int j = 0; j < 16; j++) ab[3 + j] = f2tff(rad[j]);
    ab[19] = (float)(end - beg);    // small int, exact in tf32
    #pragma unroll
    for (int j = 20; j < 32; j++) ab[j] = 0.f;
}

// transpose weights [K][N] -> [N][kpad], pre-rounded to tf32
__global__ void trans_kernel(const float* __restrict__ src, float* __restrict__ dst,
                             int K, int N, int kpad) {
    int idx = blockIdx.x * 256 + threadIdx.x;
    if (idx >= N * kpad) return;
    int n = idx / kpad, k = idx % kpad;
    float v = (k < K) ? src[(long)k * N + n] : 0.f;
    dst[idx] = f2tff(v);
}

__global__ void packT_kernel(const float* __restrict__ convW, const float* __restrict__ convB) {
    int idx = blockIdx.x * 256 + threadIdx.x;
    const int total = LL * HH * KPAD;
    if (idx >= total) return;
    int l = idx / (HH * KPAD);
    int rem = idx % (HH * KPAD);
    int n = rem / KPAD;
    int k = rem % KPAD;
    float v = 0.f;
    if (k < 275)       v = convW[((long)l * 275 + k) * HH + n];
    else if (k == 275) v = convB[l * HH + n];
    g_WpackT[idx] = f2tff(v);
}

// round + pad A matrix: dst[r][0..kpad) = tf32(src[r][0..K)), zeros beyond
__global__ void roundpad_kernel(const float* __restrict__ src, float* __restrict__ dst,
                                int K, int kpad, int M) {
    int idx = blockIdx.x * 256 + threadIdx.x;
    if (idx >= M * kpad) return;   // M*kpad < 2^31 for all uses
    int r = idx / kpad, k = idx % kpad;
    float v = (k < K) ? src[(long)r * K + k] : 0.f;
    dst[idx] = f2tff(v);
}

// ---------------- cp.async pipelined TF32 MMA GEMM ----------------
// C[M x Nt] = act(A[M x kpad] @ Bt[Nt x kpad]^T + bias); A,Bt pre-rounded tf32.
// BM=128, BN=128, BK=32, STAGES=4; 8 warps (2x4); warp tile 64x32.
#define AST 36                         // smem row stride (floats)
#define STG_FLTS (2 * 128 * AST)       // A part + B part per stage
#define GEMM_DSM (4 * STG_FLTS * 4)    // 147456 bytes
__global__ __launch_bounds__(256, 1)
void cp_gemm_kernel(const float* __restrict__ A, int lda, int M,
                    const float* __restrict__ Bt, int ldb, int Nt,
                    const float* __restrict__ bias, float* __restrict__ C, int ldc,
                    int act, int roundOut) {
    extern __shared__ float sm[];
    int t = threadIdx.x;
    int lane = t & 31, warp = t >> 5;
    int wr = warp >> 2;     // 0..1
    int wc = warp & 3;      // 0..3
    int rowBase = blockIdx.x * 128;
    int colBase = blockIdx.y * 128;
    uint32_t smb = smem_u32(sm);

    int nT = lda >> 5;                       // K chunks of 32 (lda == kpad)
    int bRows = (Nt < 128) ? Nt : 128;
    int bChunks = bRows * 8;

    float acc[4][4][4];
    #pragma unroll
    for (int mi = 0; mi < 4; mi++)
        #pragma unroll
        for (int ni = 0; ni < 4; ni++)
            #pragma unroll
            for (int q = 0; q < 4; q++) acc[mi][ni][q] = 0.f;

    // ---- stage loader (cp.async 16B chunks) ----
    auto load_stage = [&](int i, int s) {
        int k0 = i << 5;
        uint32_t sbase = smb + (uint32_t)(s * STG_FLTS) * 4u;
        #pragma unroll
        for (int it = 0; it < 4; it++) {            // A: 1024 chunks
            int c = it * 256 + t;
            int row = c >> 3, cq = c & 7;
            int gr = rowBase + row;
            if (gr >= M) gr = M - 1;
            const float* src = A + (long)gr * lda + k0 + cq * 4;
            uint32_t dst = sbase + (uint32_t)(row * AST + cq * 4) * 4u;
            CP_ASYNC16(dst, src);
        }
        for (int c = t; c < bChunks; c += 256) {    // B: bRows*8 chunks
            int n = c >> 3, cq = c & 7;
            const float* src = Bt + (long)(colBase + n) * ldb + k0 + cq * 4;
            uint32_t dst = sbase + (uint32_t)(128 * AST + n * AST + cq * 4) * 4u;
            CP_ASYNC16(dst, src);
        }
    };

    // prologue: stages 0..2 (empty commits keep group accounting uniform)
    #pragma unroll
    for (int s = 0; s < 3; s++) {
        if (s < nT) load_stage(s, s);
        CP_COMMIT();
    }

    int kq = lane & 3;
    int kg = lane >> 2;

    for (int i = 0; i < nT; i++) {
        CP_WAIT2();
        __syncthreads();
        if (i + 3 < nT) load_stage(i + 3, (i + 3) & 3);
        CP_COMMIT();

        const float* As = sm + (i & 3) * STG_FLTS;
        const float* Bs = As + 128 * AST;
        #pragma unroll
        for (int kk = 0; kk < 4; kk++) {
            int ko = kk * 8;
            unsigned af[4][4], bf[4][2];
            #pragma unroll
            for (int mi = 0; mi < 4; mi++) {
                int ar = wr * 64 + mi * 16 + kg;
                af[mi][0] = __float_as_uint(As[ar * AST + ko + kq]);
                af[mi][1] = __float_as_uint(As[(ar + 8) * AST + ko + kq]);
                af[mi][2] = __float_as_uint(As[ar * AST + ko + kq + 4]);
                af[mi][3] = __float_as_uint(As[(ar + 8) * AST + ko + kq + 4]);
            }
            #pragma unroll
            for (int ni = 0; ni < 4; ni++) {
                int bn = wc * 32 + ni * 8 + kg;
                bf[ni][0] = __float_as_uint(Bs[bn * AST + ko + kq]);
                bf[ni][1] = __float_as_uint(Bs[bn * AST + ko + kq + 4]);
            }
            #pragma unroll
            for (int mi = 0; mi < 4; mi++)
                #pragma unroll
                for (int ni = 0; ni < 4; ni++) {
                    asm volatile(
                        "mma.sync.aligned.m16n8k8.row.col.f32.tf32.tf32.f32 "
                        "{%0,%1,%2,%3}, {%4,%5,%6,%7}, {%8,%9}, {%0,%1,%2,%3};"
                        : "+f"(acc[mi][ni][0]), "+f"(acc[mi][ni][1]),
                          "+f"(acc[mi][ni][2]), "+f"(acc[mi][ni][3])
                        : "r"(af[mi][0]), "r"(af[mi][1]), "r"(af[mi][2]), "r"(af[mi][3]),
                          "r"(bf[ni][0]), "r"(bf[ni][1]));
                }
        }
        __syncthreads();
    }

    // epilogue: direct stores (bias + act + optional tf32 round fused)
    #pragma unroll
    for (int mi = 0; mi < 4; mi++) {
        #pragma unroll
        for (int ni = 0; ni < 4; ni++) {
            int r0 = rowBase + wr * 64 + mi * 16 + kg;
            int c0 = colBase + wc * 32 + ni * 8 + kq * 2;
            #pragma unroll
            for (int half = 0; half < 2; half++) {
                int r = r0 + half * 8;
                if (r >= M) continue;
                #pragma unroll
                for (int q = 0; q < 2; q++) {
                    int c = c0 + q;
                    if (c >= Nt) continue;
                    float v = acc[mi][ni][half * 2 + q] + (bias ? bias[c] : 0.f);
                    if (act) v = silu_f(v);
                    if (roundOut) v = f2tff(v);
                    C[(long)r * ldc + c] = v;
                }
            }
        }
    }
}

// ---------------- LayerNorm (warp per row of 256) ----------------
__global__ void ln_kernel(const float* __restrict__ in, const float* __restrict__ g,
                          const float* __restrict__ b, float* __restrict__ out, int M) {
    int w = (blockIdx.x * blockDim.x + threadIdx.x) >> 5;
    int lane = threadIdx.x & 31;
    if (w >= M) return;
    const float* ip = in + (long)w * HH;
    float x[8];
    float s = 0.f;
    #pragma unroll
    for (int i = 0; i < 8; i++) { x[i] = ip[lane + 32 * i]; s += x[i]; }
    s = warp_sum(s);
    float m = s * (1.f / 256.f);
    float q = 0.f;
    #pragma unroll
    for (int i = 0; i < 8; i++) { float d = x[i] - m; q += d * d; }
    q = warp_sum(q);
    float rs = rsqrtf(q * (1.f / 256.f) + 1e-5f);
    float* op = out + (long)w * HH;
    #pragma unroll
    for (int i = 0; i < 8; i++) {
        int c = lane + 32 * i;
        op[c] = (x[i] - m) * rs * g[c] + b[c];
    }
}

// ---------------- gather: Hsum[n] = sum_e h[src_e]; store tf32-rounded ----------------
__global__ void gather_kernel() {
    int w = (blockIdx.x * 256 + threadIdx.x) >> 5;
    int lane = threadIdx.x & 31;
    if (w >= NN) return;
    float4 a0 = make_float4(0.f, 0.f, 0.f, 0.f);
    float4 a1 = make_float4(0.f, 0.f, 0.f, 0.f);
    float4 c0 = make_float4(0.f, 0.f, 0.f, 0.f);
    float4 c1 = make_float4(0.f, 0.f, 0.f, 0.f);
    int beg = g_rowptr[w], end = g_rowptr[w + 1];
    int e = beg;
    for (; e + 1 < end; e += 2) {
        int s0 = g_csrc[e];
        int s1 = g_csrc[e + 1];
        const float4* h0 = (const float4*)(g_h + (long)s0 * HH);
        const float4* h1 = (const float4*)(g_h + (long)s1 * HH);
        float4 v0 = h0[lane];
        float4 v1 = h0[lane + 32];
        float4 u0 = h1[lane];
        float4 u1 = h1[lane + 32];
        a0.x += v0.x; a0.y += v0.y; a0.z += v0.z; a0.w += v0.w;
        a1.x += v1.x; a1.y += v1.y; a1.z += v1.z; a1.w += v1.w;
        c0.x += u0.x; c0.y += u0.y; c0.z += u0.z; c0.w += u0.w;
        c1.x += u1.x; c1.y += u1.y; c1.z += u1.z; c1.w += u1.w;
    }
    if (e < end) {
        int s0 = g_csrc[e];
        const float4* h0 = (const float4*)(g_h + (long)s0 * HH);
        float4 v0 = h0[lane];
        float4 v1 = h0[lane + 32];
        a0.x += v0.x; a0.y += v0.y; a0.z += v0.z; a0.w += v0.w;
        a1.x += v1.x; a1.y += v1.y; a1.z += v1.z; a1.w += v1.w;
    }
    a0.x = f2tff(a0.x + c0.x); a0.y = f2tff(a0.y + c0.y);
    a0.z = f2tff(a0.z + c0.z); a0.w = f2tff(a0.w + c0.w);
    a1.x = f2tff(a1.x + c1.x); a1.y = f2tff(a1.y + c1.y);
    a1.z = f2tff(a1.z + c1.z); a1.w = f2tff(a1.w + c1.w);
    float4* ap = (float4*)(g_Abuf + (long)w * KPAD);
    ap[lane] = a0;
    ap[lane + 32] = a1;
}

// ---------------- post-conv: h = LN(h + LN(silu(agg))) ----------------
__global__ void postconv_kernel(const float* __restrict__ cg, const float* __restrict__ cb,
                                const float* __restrict__ lg, const float* __restrict__ lb) {
    int w = (blockIdx.x * 256 + threadIdx.x) >> 5;
    int lane = threadIdx.x & 31;
    if (w >= NN) return;
    const float* ap = g_agg + (long)w * HH;
    float* hp = g_h + (long)w * HH;
    float x[8];
    float s = 0.f;
    #pragma unroll
    for (int i = 0; i < 8; i++) {
        float a = ap[lane + 32 * i];
        float v = silu_f(a);
        x[i] = v; s += v;
    }
    s = warp_sum(s);
    float m1 = s * (1.f / 256.f);
    float q = 0.f;
    #pragma unroll
    for (int i = 0; i < 8; i++) { float d = x[i] - m1; q += d * d; }
    q = warp_sum(q);
    float rs1 = rsqrtf(q * (1.f / 256.f) + 1e-5f);
    float z[8];
    float s2 = 0.f;
    #pragma unroll
    for (int i = 0; i < 8; i++) {
        int c = lane + 32 * i;
        float y = (x[i] - m1) * rs1 * cg[c] + cb[c];
        float zz = hp[c] + y;
        z[i] = zz; s2 += zz;
    }
    s2 = warp_sum(s2);
    float m2 = s2 * (1.f / 256.f);
    float q2 = 0.f;
    #pragma unroll
    for (int i = 0; i < 8; i++) { float d = z[i] - m2; q2 += d * d; }
    q2 = warp_sum(q2);
    float rs2 = rsqrtf(q2 * (1.f / 256.f) + 1e-5f);
    #pragma unroll
    for (int i = 0; i < 8; i++) {
        int c = lane + 32 * i;
        hp[c] = (z[i] - m2) * rs2 * lg[c] + lb[c];
    }
}

// ---------------- pooling ----------------
__global__ void gate_kernel(const float* __restrict__ pgW2, const float* __restrict__ pgb2) {
    int w = (blockIdx.x * 256 + threadIdx.x) >> 5;
    int lane = threadIdx.x & 31;
    if (w >= NN) return;
    float v = g_gatev[(long)w * 64 + lane] * pgW2[lane]
            + g_gatev[(long)w * 64 + 32 + lane] * pgW2[32 + lane];
    v = warp_sum(v);
    if (lane == 0) g_gate[w] = v + pgb2[0];
}

__global__ void maxpart_kernel() {
    __shared__ float sm[256];
    int tid = threadIdx.x;
    float m = -1e30f;
    for (int i = blockIdx.x * 256 + tid; i < NN; i += gridDim.x * 256)
        m = fmaxf(m, g_gate[i]);
    sm[tid] = m;
    __syncthreads();
    for (int o = 128; o; o >>= 1) {
        if (tid < o) sm[tid] = fmaxf(sm[tid], sm[tid + o]);
        __syncthreads();
    }
    if (tid == 0) g_partial[blockIdx.x] = sm[0];
}

__global__ void maxfin_kernel(int nb) {
    __shared__ float sm[256];
    int tid = threadIdx.x;
    sm[tid] = (tid < nb) ? g_partial[tid] : -1e30f;
    __syncthreads();
    for (int o = 128; o; o >>= 1) {
        if (tid < o) sm[tid] = fmaxf(sm[tid], sm[tid + o]);
        __syncthreads();
    }
    if (tid == 0) g_scal[0] = sm[0];
}

__global__ void expsum_kernel() {
    __shared__ float sm[256];
    int tid = threadIdx.x;
    int i = blockIdx.x * 256 + tid;
    float M = g_scal[0];
    float e = 0.f;
    if (i < NN) { e = expf(g_gate[i] - M); g_e[i] = e; }
    sm[tid] = e;
    __syncthreads();
    for (int o = 128; o; o >>= 1) {
        if (tid < o) sm[tid] += sm[tid + o];
        __syncthreads();
    }
    if (tid == 0) atomicAdd(&g_scal[1], sm[0]);
}

__global__ void wsum_kernel() {
    int t = threadIdx.x;
    int n0 = blockIdx.x * 256;
    float acc = 0.f;
    for (int i = 0; i < 256; i++) {
        int n = n0 + i;
        if (n >= NN) break;
        acc += g_e[n] * g_h[(long)n * HH + t];
    }
    atomicAdd(&g_Gvec[t], acc);
}

// round h into scratch for pool GEMM A
__global__ void roundh_kernel(float* __restrict__ dst) {
    int i = blockIdx.x * 256 + threadIdx.x;
    if (i < NN * HH) dst[i] = f2tff(g_h[i]);
}

// ---------------- heads (single block) ----------------
__global__ void heads_kernel(const float* __restrict__ clW1, const float* __restrict__ clb1,
                             const float* __restrict__ clW2, const float* __restrict__ clb2,
                             const float* __restrict__ prW1, const float* __restrict__ prb1,
                             const float* __restrict__ prW2, const float* __restrict__ prb2,
                             float* __restrict__ out) {
    __shared__ float emb[256], c1[128], p1[256], pr[128];
    __shared__ float nrm;
    int t = threadIdx.x;
    float se = g_scal[1];
    float ev = g_Gvec[t] / se;
    emb[t] = ev;
    out[132 + t] = ev;
    __syncthreads();
    if (t < 128) {
        float a = 0.f;
        for (int k = 0; k < 256; k++) a += emb[k] * clW1[k * 128 + t];
        a += clb1[t];
        c1[t] = silu_f(a);
    }
    {
        float a = 0.f;
        for (int k = 0; k < 256; k++) a += emb[k] * prW1[k * 256 + t];
        a += prb1[t];
        p1[t] = silu_f(a);
    }
    __syncthreads();
    if (t < 4) {
        float a = 0.f;
        for (int k = 0; k < 128; k++) a += c1[k] * clW2[k * 4 + t];
        out[t] = a + clb2[t];
    }
    if (t < 128) {
        float a = 0.f;
        for (int k = 0; k < 256; k++) a += p1[k] * prW2[k * 128 + t];
        pr[t] = a + prb2[t];
    }
    __syncthreads();
    if (t == 0) {
        float s = 0.f;
        for (int k = 0; k < 128; k++) s += pr[k] * pr[k];
        nrm = fmaxf(sqrtf(s), 1e-12f);
    }
    __syncthreads();
    if (t < 128) out[4 + t] = pr[t] / nrm;
}

// ---------------- launch ----------------
extern "C" void kernel_launch(void* const* d_in, const int* in_sizes, int n_in,
                              void* d_out, int out_size) {
    const float* x       = (const float*)d_in[0];
    const float* pos     = (const float*)d_in[1];
    const int*   ei      = (const int*)d_in[2];
    const float* ne_W1   = (const float*)d_in[3];
    const float* ne_b1   = (const float*)d_in[4];
    const float* ne_W2   = (const float*)d_in[5];
    const float* ne_b2   = (const float*)d_in[6];
    const float* ne_g    = (const float*)d_in[7];
    const float* ne_beta = (const float*)d_in[8];
    const float* convW   = (const float*)d_in[9];
    const float* convB   = (const float*)d_in[10];
    const float* convG   = (const float*)d_in[11];
    const float* convBeta= (const float*)d_in[12];
    const float* lnG     = (const float*)d_in[13];
    const float* lnB     = (const float*)d_in[14];
    const float* pgW1    = (const float*)d_in[15];
    const float* pgb1    = (const float*)d_in[16];
    const float* pgW2    = (const float*)d_in[17];
    const float* pgb2    = (const float*)d_in[18];
    const float* clW1    = (const float*)d_in[19];
    const float* clb1    = (const float*)d_in[20];
    const float* clW2    = (const float*)d_in[21];
    const float* clb2    = (const float*)d_in[22];
    const float* prW1    = (const float*)d_in[23];
    const float* prb1    = (const float*)d_in[24];
    const float* prW2    = (const float*)d_in[25];
    const float* prb2    = (const float*)d_in[26];
    float* out = (float*)d_out;

    float *p_xr, *p_t1, *p_h, *p_Abuf, *p_agg, *p_gatev;
    float *p_W1t, *p_W2t, *p_pgW1t, *p_WpackT;
    cudaGetSymbolAddress((void**)&p_xr, g_xr);
    cudaGetSymbolAddress((void**)&p_t1, g_t1);
    cudaGetSymbolAddress((void**)&p_h, g_h);
    cudaGetSymbolAddress((void**)&p_Abuf, g_Abuf);
    cudaGetSymbolAddress((void**)&p_agg, g_agg);
    cudaGetSymbolAddress((void**)&p_gatev, g_gatev);
    cudaGetSymbolAddress((void**)&p_W1t, g_W1t);
    cudaGetSymbolAddress((void**)&p_W2t, g_W2t);
    cudaGetSymbolAddress((void**)&p_pgW1t, g_pgW1t);
    cudaGetSymbolAddress((void**)&p_WpackT, g_WpackT);

    cudaFuncSetAttribute(cp_gemm_kernel, cudaFuncAttributeMaxDynamicSharedMemorySize, GEMM_DSM);

    const int EB = (EE + 255) / 256;
    const int NB = (NN + 255) / 256;
    const int WB = (NN + 7) / 8;
    const int MB = (NN + 127) / 128;
    const int SB = (NN + 1023) / 1024;

    // setup
    zero_kernel<<<NB, 256>>>();
    edge1_kernel<<<EB, 256>>>(ei);
    scan1_kernel<<<SB, 1024>>>();
    scan2_kernel<<<1, 64>>>(SB);
    scan3_kernel<<<NB, 256>>>();
    edge2_kernel<<<EB, 256>>>(ei);
    ef_kernel<<<NB, 256>>>(pos);
    trans_kernel<<<(HH * K1PAD + 255) / 256, 256>>>(ne_W1, p_W1t, NIN, HH, K1PAD);
    trans_kernel<<<(HH * HH + 255) / 256, 256>>>(ne_W2, p_W2t, HH, HH, HH);
    trans_kernel<<<(64 * HH + 255) / 256, 256>>>(pgW1, p_pgW1t, HH, 64, HH);
    packT_kernel<<<(LL * HH * KPAD + 255) / 256, 256>>>(convW, convB);
    roundpad_kernel<<<(NN * K1PAD + 255) / 256, 256>>>(x, p_xr, NIN, K1PAD, NN);

    // node encoder
    cp_gemm_kernel<<<dim3(MB, 2), 256, GEMM_DSM>>>(p_xr, K1PAD, NN, p_W1t, K1PAD, 256,
                                                   ne_b1, p_t1, HH, 1, 1);
    cp_gemm_kernel<<<dim3(MB, 2), 256, GEMM_DSM>>>(p_t1, HH, NN, p_W2t, HH, 256,
                                                   ne_b2, p_agg, HH, 0, 0);
    ln_kernel<<<WB, 256>>>(p_agg, ne_g, ne_beta, p_h, NN);

    // conv layers
    for (int l = 0; l < LL; l++) {
        gather_kernel<<<WB, 256>>>();
        cp_gemm_kernel<<<dim3(MB, 2), 256, GEMM_DSM>>>(p_Abuf, KPAD, NN,
                                                       p_WpackT + (long)l * HH * KPAD, KPAD, 256,
                                                       nullptr, p_agg, HH, 0, 0);
        postconv_kernel<<<WB, 256>>>(convG + l * HH, convBeta + l * HH,
                                     lnG + l * HH, lnB + l * HH);
    }

    // attention pooling (A = tf32-rounded h, reusing g_xr as scratch)
    roundh_kernel<<<(NN * HH + 255) / 256, 256>>>(p_xr);
    cp_gemm_kernel<<<dim3(MB, 1), 256, GEMM_DSM>>>(p_xr, HH, NN, p_pgW1t, HH, 64,
                                                   pgb1, p_gatev, 64, 1, 0);
    gate_kernel<<<WB, 256>>>(pgW2, pgb2);
    maxpart_kernel<<<64, 256>>>();
    maxfin_kernel<<<1, 256>>>(64);
    expsum_kernel<<<NB, 256>>>();
    wsum_kernel<<<NB, 256>>>();

    // heads
    heads_kernel<<<1, 256>>>(clW1, clb1, clW2, clb2, prW1, prb1, prW2, prb2, out);
}

// round 7
// speedup vs baseline: 2.1994x; 1.0563x over previous
#include <cuda_runtime.h>
#include <math.h>
#include <stdint.h>

#define NN 50000
#define EE 1000000
#define NIN 1281
#define K1PAD 1312
#define HH 256
#define LL 4
#define KPAD 288            // 256 Hsum + 3 sh + 16 radial + 1 deg + 12 zero pad

// ---------------- scratch (device globals; no runtime allocation) ----------------
__device__ float g_t1[NN * HH];
__device__ float g_h[NN * HH];
__device__ float g_Abuf[NN * KPAD];
__device__ float g_agg[NN * HH];
__device__ float g_gatev[NN * 64];
__device__ float g_gate[NN];
__device__ float g_e[NN];
__device__ int   g_deg[NN];
__device__ int   g_rowptr[NN + 1];
__device__ int   g_cursor[NN];
__device__ int   g_csrc[EE];
__device__ float g_W1t[HH * K1PAD];        // ne_W1 transposed [256][1312], tf32-rounded
__device__ float g_W2t[HH * HH];
__device__ float g_pgW1t[64 * HH];
__device__ float g_WpackT[LL * HH * KPAD];
__device__ float g_partial[256];
__device__ float g_scal[4];
__device__ float g_Gvec[HH];
__device__ int   g_bsum[64];

// ---------------- helpers ----------------
__device__ __forceinline__ float warp_sum(float v) {
    #pragma unroll
    for (int o = 16; o; o >>= 1) v += __shfl_xor_sync(0xffffffffu, v, o);
    return v;
}
__device__ __forceinline__ float silu_f(float x) { return x / (1.f + expf(-x)); }
__device__ __forceinline__ unsigned f2tf(float f) {
    unsigned r;
    asm("cvt.rna.tf32.f32 %0, %1;" : "=r"(r) : "f"(f));
    return r;
}
__device__ __forceinline__ float f2tff(float f) { return __uint_as_float(f2tf(f)); }
__device__ __forceinline__ uint32_t smem_u32(const void* p) {
    uint32_t a;
    asm("{ .reg .u64 t; cvta.to.shared.u64 t, %1; cvt.u32.u64 %0, t; }" : "=r"(a) : "l"(p));
    return a;
}
#define CP_ASYNC16(dst, src) \
    asm volatile("cp.async.ca.shared.global [%0], [%1], 16;" :: "r"(dst), "l"(src))
#define CP_ASYNC4Z(dst, src, sz) \
    asm volatile("cp.async.ca.shared.global [%0], [%1], 4, %2;" :: "r"(dst), "l"(src), "r"(sz))
#define CP_COMMIT() asm volatile("cp.async.commit_group;" ::: "memory")
#define CP_WAIT1()  asm volatile("cp.async.wait_group 1;" ::: "memory")

// ---------------- setup kernels ----------------
__global__ void zero_kernel() {
    int i = blockIdx.x * 256 + threadIdx.x;
    if (i < NN) { g_deg[i] = 0; g_cursor[i] = 0; }
    if (i < HH) g_Gvec[i] = 0.f;
    if (i < 4) g_scal[i] = 0.f;
    if (i == 0) g_rowptr[0] = 0;
}

__global__ void edge1_kernel(const int* __restrict__ ei) {
    int e = blockIdx.x * 256 + threadIdx.x;
    if (e >= EE) return;
    atomicAdd(&g_deg[ei[EE + e]], 1);
}

__global__ void scan1_kernel() {
    __shared__ int s[1024];
    int tid = threadIdx.x;
    int gid = blockIdx.x * 1024 + tid;
    int v = (gid < NN) ? g_deg[gid] : 0;
    s[tid] = v;
    __syncthreads();
    for (int off = 1; off < 1024; off <<= 1) {
        int t = (tid >= off) ? s[tid - off] : 0;
        __syncthreads();
        s[tid] += t;
        __syncthreads();
    }
    if (gid < NN) g_rowptr[gid + 1] = s[tid];
    if (tid == 1023) g_bsum[blockIdx.x] = s[1023];
}

__global__ void scan2_kernel(int nb) {
    __shared__ int s[64];
    int tid = threadIdx.x;
    s[tid] = (tid < nb) ? g_bsum[tid] : 0;
    __syncthreads();
    for (int off = 1; off < 64; off <<= 1) {
        int t = (tid >= off) ? s[tid - off] : 0;
        __syncthreads();
        s[tid] += t;
        __syncthreads();
    }
    if (tid < nb) g_bsum[tid] = s[tid];
}

__global__ void scan3_kernel() {
    int gid = blockIdx.x * 256 + threadIdx.x;
    if (gid >= NN) return;
    int b = gid >> 10;
    if (b > 0) g_rowptr[gid + 1] += g_bsum[b - 1];
}

__global__ void edge2_kernel(const int* __restrict__ ei) {
    int e = blockIdx.x * 256 + threadIdx.x;
    if (e >= EE) return;
    int s = ei[e];
    int d = ei[EE + e];
    int slot = atomicAdd(&g_cursor[d], 1);
    g_csrc[g_rowptr[d] + slot] = s;
}

__global__ void ef_kernel(const float* __restrict__ pos) {
    int n = blockIdx.x * 256 + threadIdx.x;
    if (n >= NN) return;
    const float w = 0.1953125f;
    const float cstep = 10.f / 15.f;
    float Ej[16];
    #pragma unroll
    for (int j = 0; j < 16; j++) {
        float c = cstep * (float)j;
        Ej[j] = expf(-w * c * c);
    }
    float px = pos[3 * n + 0], py = pos[3 * n + 1], pz = pos[3 * n + 2];
    float shx = 0.f, shy = 0.f, shz = 0.f;
    float rad[16];
    #pragma unroll
    for (int j = 0; j < 16; j++) rad[j] = 0.f;
    int beg = g_rowptr[n], end = g_rowptr[n + 1];
    for (int e = beg; e < end; e++) {
        int s = g_csrc[e];
        float rx = px - pos[3 * s + 0];
        float ry = py - pos[3 * s + 1];
        float rz = pz - pos[3 * s + 2];
        float dist = sqrtf(rx * rx + ry * ry + rz * rz);
        float inv = 1.f / fmaxf(dist, 1e-12f);
        shx += rx * inv; shy += ry * inv; shz += rz * inv;
        if (dist < 18.f) {
            float A = expf(-w * dist * dist);
            float r = expf(2.f * w * cstep * dist);
            float p = A;
            #pragma unroll
            for (int j = 0; j < 16; j++) {
                rad[j] += p * Ej[j];
                p *= r;
            }
        } else {
            #pragma unroll
            for (int j = 0; j < 16; j++) {
                float t = dist - cstep * (float)j;
                rad[j] += expf(-w * t * t);
            }
        }
    }
    float* ab = g_Abuf + (long)n * KPAD + 256;
    ab[0] = f2tff(shx); ab[1] = f2tff(shy); ab[2] = f2tff(shz);
    #pragma unroll
    for (int j = 0; j < 16; j++) ab[3 + j] = f2tff(rad[j]);
    ab[19] = (float)(end - beg);
    #pragma unroll
    for (int j = 20; j < 32; j++) ab[j] = 0.f;
}

// transpose weights [K][N] -> [N][kpad], pre-rounded to tf32
__global__ void trans_kernel(const float* __restrict__ src, float* __restrict__ dst,
                             int K, int N, int kpad) {
    int idx = blockIdx.x * 256 + threadIdx.x;
    if (idx >= N * kpad) return;
    int n = idx / kpad, k = idx % kpad;
    float v = (k < K) ? src[(long)k * N + n] : 0.f;
    dst[idx] = f2tff(v);
}

__global__ void packT_kernel(const float* __restrict__ convW, const float* __restrict__ convB) {
    int idx = blockIdx.x * 256 + threadIdx.x;
    const int total = LL * HH * KPAD;
    if (idx >= total) return;
    int l = idx / (HH * KPAD);
    int rem = idx % (HH * KPAD);
    int n = rem / KPAD;
    int k = rem % KPAD;
    float v = 0.f;
    if (k < 275)       v = convW[((long)l * 275 + k) * HH + n];
    else if (k == 275) v = convB[l * HH + n];
    g_WpackT[idx] = f2tff(v);
}

// ---------------- cp.async pipelined TF32 MMA GEMM (3-stage, occ 2) ----------------
// C[M x Nt] = act(A[M x K] @ Bt[Nt x ldb]^T + bias).
// Bt pre-rounded tf32 + zero-padded to >=ceil32(K). A raw f32 if cvtA (fragment cvt).
#define AST 36                         // smem row stride (floats)
#define STG_FLTS (2 * 128 * AST)       // A + B per stage
#define GEMM_DSM (3 * STG_FLTS * 4)    // 110592 bytes
__global__ __launch_bounds__(256, 2)
void cp_gemm_kernel(const float* __restrict__ A, int lda, int M, int K,
                    const float* __restrict__ Bt, int ldb, int Nt,
                    const float* __restrict__ bias, float* __restrict__ C, int ldc,
                    int act, int roundOut, int cvtA) {
    extern __shared__ float sm[];
    int t = threadIdx.x;
    int lane = t & 31, warp = t >> 5;
    int wr = warp >> 2;
    int wc = warp & 3;
    int rowBase = blockIdx.x * 128;
    int colBase = blockIdx.y * 128;
    uint32_t smb = smem_u32(sm);

    int nT = (K + 31) >> 5;
    int aElem = (lda & 3) != 0;               // unaligned rows -> 4B cp.async w/ zfill
    int bRows = (Nt < 128) ? Nt : 128;
    int bChunks = bRows * 8;

    float acc[4][4][4];
    #pragma unroll
    for (int mi = 0; mi < 4; mi++)
        #pragma unroll
        for (int ni = 0; ni < 4; ni++)
            #pragma unroll
            for (int q = 0; q < 4; q++) acc[mi][ni][q] = 0.f;

    auto load_stage = [&](int i, int s) {
        int k0 = i << 5;
        uint32_t sbase = smb + (uint32_t)(s * STG_FLTS) * 4u;
        if (aElem) {
            #pragma unroll
            for (int it = 0; it < 4; it++) {
                int c = it * 256 + t;
                int row = c >> 3, cq = c & 7;
                int gr = rowBase + row;
                if (gr >= M) gr = M - 1;
                long rb = (long)gr * lda;
                uint32_t dst = sbase + (uint32_t)(row * AST + cq * 4) * 4u;
                #pragma unroll
                for (int j = 0; j < 4; j++) {
                    int gk = k0 + cq * 4 + j;
                    int ck = (gk < K) ? gk : (K - 1);
                    int sz = (gk < K) ? 4 : 0;
                    CP_ASYNC4Z(dst + j * 4, A + rb + ck, sz);
                }
            }
        } else {
            #pragma unroll
            for (int it = 0; it < 4; it++) {
                int c = it * 256 + t;
                int row = c >> 3, cq = c & 7;
                int gr = rowBase + row;
                if (gr >= M) gr = M - 1;
                const float* src = A + (long)gr * lda + k0 + cq * 4;
                uint32_t dst = sbase + (uint32_t)(row * AST + cq * 4) * 4u;
                CP_ASYNC16(dst, src);
            }
        }
        for (int c = t; c < bChunks; c += 256) {
            int n = c >> 3, cq = c & 7;
            const float* src = Bt + (long)(colBase + n) * ldb + k0 + cq * 4;
            uint32_t dst = sbase + (uint32_t)(128 * AST + n * AST + cq * 4) * 4u;
            CP_ASYNC16(dst, src);
        }
    };

    // prologue: stages 0,1
    load_stage(0, 0);
    CP_COMMIT();
    if (nT > 1) load_stage(1, 1);
    CP_COMMIT();

    int kq = lane & 3;
    int kg = lane >> 2;

    for (int i = 0; i < nT; i++) {
        CP_WAIT1();
        __syncthreads();
        if (i + 2 < nT) {
            int s = (i + 2) % 3;
            load_stage(i + 2, s);
        }
        CP_COMMIT();

        const float* As = sm + (i % 3) * STG_FLTS;
        const float* Bs = As + 128 * AST;
        #pragma unroll
        for (int kk = 0; kk < 4; kk++) {
            int ko = kk * 8;
            unsigned af[4][4], bf[4][2];
            #pragma unroll
            for (int mi = 0; mi < 4; mi++) {
                int ar = wr * 64 + mi * 16 + kg;
                af[mi][0] = __float_as_uint(As[ar * AST + ko + kq]);
                af[mi][1] = __float_as_uint(As[(ar + 8) * AST + ko + kq]);
                af[mi][2] = __float_as_uint(As[ar * AST + ko + kq + 4]);
                af[mi][3] = __float_as_uint(As[(ar + 8) * AST + ko + kq + 4]);
            }
            if (cvtA) {
                #pragma unroll
                for (int mi = 0; mi < 4; mi++)
                    #pragma unroll
                    for (int q = 0; q < 4; q++)
                        af[mi][q] = f2tf(__uint_as_float(af[mi][q]));
            }
            #pragma unroll
            for (int ni = 0; ni < 4; ni++) {
                int bn = wc * 32 + ni * 8 + kg;
                bf[ni][0] = __float_as_uint(Bs[bn * AST + ko + kq]);
                bf[ni][1] = __float_as_uint(Bs[bn * AST + ko + kq + 4]);
            }
            #pragma unroll
            for (int mi = 0; mi < 4; mi++)
                #pragma unroll
                for (int ni = 0; ni < 4; ni++) {
                    asm volatile(
                        "mma.sync.aligned.m16n8k8.row.col.f32.tf32.tf32.f32 "
                        "{%0,%1,%2,%3}, {%4,%5,%6,%7}, {%8,%9}, {%0,%1,%2,%3};"
                        : "+f"(acc[mi][ni][0]), "+f"(acc[mi][ni][1]),
                          "+f"(acc[mi][ni][2]), "+f"(acc[mi][ni][3])
                        : "r"(af[mi][0]), "r"(af[mi][1]), "r"(af[mi][2]), "r"(af[mi][3]),
                          "r"(bf[ni][0]), "r"(bf[ni][1]));
                }
        }
    }

    // epilogue
    #pragma unroll
    for (int mi = 0; mi < 4; mi++) {
        #pragma unroll
        for (int ni = 0; ni < 4; ni++) {
            int r0 = rowBase + wr * 64 + mi * 16 + kg;
            int c0 = colBase + wc * 32 + ni * 8 + kq * 2;
            #pragma unroll
            for (int half = 0; half < 2; half++) {
                int r = r0 + half * 8;
                if (r >= M) continue;
                #pragma unroll
                for (int q = 0; q < 2; q++) {
                    int c = c0 + q;
                    if (c >= Nt) continue;
                    float v = acc[mi][ni][half * 2 + q] + (bias ? bias[c] : 0.f);
                    if (act) v = silu_f(v);
                    if (roundOut) v = f2tff(v);
                    C[(long)r * ldc + c] = v;
                }
            }
        }
    }
}

// ---------------- LayerNorm (warp per row of 256) ----------------
__global__ void ln_kernel(const float* __restrict__ in, const float* __restrict__ g,
                          const float* __restrict__ b, float* __restrict__ out, int M) {
    int w = (blockIdx.x * blockDim.x + threadIdx.x) >> 5;
    int lane = threadIdx.x & 31;
    if (w >= M) return;
    const float* ip = in + (long)w * HH;
    float x[8];
    float s = 0.f;
    #pragma unroll
    for (int i = 0; i < 8; i++) { x[i] = ip[lane + 32 * i]; s += x[i]; }
    s = warp_sum(s);
    float m = s * (1.f / 256.f);
    float q = 0.f;
    #pragma unroll
    for (int i = 0; i < 8; i++) { float d = x[i] - m; q += d * d; }
    q = warp_sum(q);
    float rs = rsqrtf(q * (1.f / 256.f) + 1e-5f);
    float* op = out + (long)w * HH;
    #pragma unroll
    for (int i = 0; i < 8; i++) {
        int c = lane + 32 * i;
        op[c] = (x[i] - m) * rs * g[c] + b[c];
    }
}

// ---------------- gather: Hsum[n] = sum_e h[src_e]; store tf32-rounded ----------------
__global__ void gather_kernel() {
    int w = (blockIdx.x * 256 + threadIdx.x) >> 5;
    int lane = threadIdx.x & 31;
    if (w >= NN) return;
    float4 a0 = make_float4(0.f, 0.f, 0.f, 0.f);
    float4 a1 = make_float4(0.f, 0.f, 0.f, 0.f);
    float4 c0 = make_float4(0.f, 0.f, 0.f, 0.f);
    float4 c1 = make_float4(0.f, 0.f, 0.f, 0.f);
    int beg = g_rowptr[w], end = g_rowptr[w + 1];
    int e = beg;
    for (; e + 1 < end; e += 2) {
        int s0 = g_csrc[e];
        int s1 = g_csrc[e + 1];
        const float4* h0 = (const float4*)(g_h + (long)s0 * HH);
        const float4* h1 = (const float4*)(g_h + (long)s1 * HH);
        float4 v0 = h0[lane];
        float4 v1 = h0[lane + 32];
        float4 u0 = h1[lane];
        float4 u1 = h1[lane + 32];
        a0.x += v0.x; a0.y += v0.y; a0.z += v0.z; a0.w += v0.w;
        a1.x += v1.x; a1.y += v1.y; a1.z += v1.z; a1.w += v1.w;
        c0.x += u0.x; c0.y += u0.y; c0.z += u0.z; c0.w += u0.w;
        c1.x += u1.x; c1.y += u1.y; c1.z += u1.z; c1.w += u1.w;
    }
    if (e < end) {
        int s0 = g_csrc[e];
        const float4* h0 = (const float4*)(g_h + (long)s0 * HH);
        float4 v0 = h0[lane];
        float4 v1 = h0[lane + 32];
        a0.x += v0.x; a0.y += v0.y; a0.z += v0.z; a0.w += v0.w;
        a1.x += v1.x; a1.y += v1.y; a1.z += v1.z; a1.w += v1.w;
    }
    a0.x = f2tff(a0.x + c0.x); a0.y = f2tff(a0.y + c0.y);
    a0.z = f2tff(a0.z + c0.z); a0.w = f2tff(a0.w + c0.w);
    a1.x = f2tff(a1.x + c1.x); a1.y = f2tff(a1.y + c1.y);
    a1.z = f2tff(a1.z + c1.z); a1.w = f2tff(a1.w + c1.w);
    float4* ap = (float4*)(g_Abuf + (long)w * KPAD);
    ap[lane] = a0;
    ap[lane + 32] = a1;
}

// ---------------- post-conv: h = LN(h + LN(silu(agg))) ----------------
__global__ void postconv_kernel(const float* __restrict__ cg, const float* __restrict__ cb,
                                const float* __restrict__ lg, const float* __restrict__ lb) {
    int w = (blockIdx.x * 256 + threadIdx.x) >> 5;
    int lane = threadIdx.x & 31;
    if (w >= NN) return;
    const float* ap = g_agg + (long)w * HH;
    float* hp = g_h + (long)w * HH;
    float x[8];
    float s = 0.f;
    #pragma unroll
    for (int i = 0; i < 8; i++) {
        float a = ap[lane + 32 * i];
        float v = silu_f(a);
        x[i] = v; s += v;
    }
    s = warp_sum(s);
    float m1 = s * (1.f / 256.f);
    float q = 0.f;
    #pragma unroll
    for (int i = 0; i < 8; i++) { float d = x[i] - m1; q += d * d; }
    q = warp_sum(q);
    float rs1 = rsqrtf(q * (1.f / 256.f) + 1e-5f);
    float z[8];
    float s2 = 0.f;
    #pragma unroll
    for (int i = 0; i < 8; i++) {
        int c = lane + 32 * i;
        float y = (x[i] - m1) * rs1 * cg[c] + cb[c];
        float zz = hp[c] + y;
        z[i] = zz; s2 += zz;
    }
    s2 = warp_sum(s2);
    float m2 = s2 * (1.f / 256.f);
    float q2 = 0.f;
    #pragma unroll
    for (int i = 0; i < 8; i++) { float d = z[i] - m2; q2 += d * d; }
    q2 = warp_sum(q2);
    float rs2 = rsqrtf(q2 * (1.f / 256.f) + 1e-5f);
    #pragma unroll
    for (int i = 0; i < 8; i++) {
        int c = lane + 32 * i;
        hp[c] = (z[i] - m2) * rs2 * lg[c] + lb[c];
    }
}

// ---------------- pooling ----------------
__global__ void gate_kernel(const float* __restrict__ pgW2, const float* __restrict__ pgb2) {
    int w = (blockIdx.x * 256 + threadIdx.x) >> 5;
    int lane = threadIdx.x & 31;
    if (w >= NN) return;
    float v = g_gatev[(long)w * 64 + lane] * pgW2[lane]
            + g_gatev[(long)w * 64 + 32 + lane] * pgW2[32 + lane];
    v = warp_sum(v);
    if (lane == 0) g_gate[w] = v + pgb2[0];
}

__global__ void maxpart_kernel() {
    __shared__ float sm[256];
    int tid = threadIdx.x;
    float m = -1e30f;
    for (int i = blockIdx.x * 256 + tid; i < NN; i += gridDim.x * 256)
        m = fmaxf(m, g_gate[i]);
    sm[tid] = m;
    __syncthreads();
    for (int o = 128; o; o >>= 1) {
        if (tid < o) sm[tid] = fmaxf(sm[tid], sm[tid + o]);
        __syncthreads();
    }
    if (tid == 0) g_partial[blockIdx.x] = sm[0];
}

__global__ void maxfin_kernel(int nb) {
    __shared__ float sm[256];
    int tid = threadIdx.x;
    sm[tid] = (tid < nb) ? g_partial[tid] : -1e30f;
    __syncthreads();
    for (int o = 128; o; o >>= 1) {
        if (tid < o) sm[tid] = fmaxf(sm[tid], sm[tid + o]);
        __syncthreads();
    }
    if (tid == 0) g_scal[0] = sm[0];
}

__global__ void expsum_kernel() {
    __shared__ float sm[256];
    int tid = threadIdx.x;
    int i = blockIdx.x * 256 + tid;
    float M = g_scal[0];
    float e = 0.f;
    if (i < NN) { e = expf(g_gate[i] - M); g_e[i] = e; }
    sm[tid] = e;
    __syncthreads();
    for (int o = 128; o; o >>= 1) {
        if (tid < o) sm[tid] += sm[tid + o];
        __syncthreads();
    }
    if (tid == 0) atomicAdd(&g_scal[1], sm[0]);
}

__global__ void wsum_kernel() {
    int t = threadIdx.x;
    int n0 = blockIdx.x * 256;
    float acc = 0.f;
    for (int i = 0; i < 256; i++) {
        int n = n0 + i;
        if (n >= NN) break;
        acc += g_e[n] * g_h[(long)n * HH + t];
    }
    atomicAdd(&g_Gvec[t], acc);
}

// ---------------- heads (single block) ----------------
__global__ void heads_kernel(const float* __restrict__ clW1, const float* __restrict__ clb1,
                             const float* __restrict__ clW2, const float* __restrict__ clb2,
                             const float* __restrict__ prW1, const float* __restrict__ prb1,
                             const float* __restrict__ prW2, const float* __restrict__ prb2,
                             float* __restrict__ out) {
    __shared__ float emb[256], c1[128], p1[256], pr[128];
    __shared__ float nrm;
    int t = threadIdx.x;
    float se = g_scal[1];
    float ev = g_Gvec[t] / se;
    emb[t] = ev;
    out[132 + t] = ev;
    __syncthreads();
    if (t < 128) {
        float a = 0.f;
        for (int k = 0; k < 256; k++) a += emb[k] * clW1[k * 128 + t];
        a += clb1[t];
        c1[t] = silu_f(a);
    }
    {
        float a = 0.f;
        for (int k = 0; k < 256; k++) a += emb[k] * prW1[k * 256 + t];
        a += prb1[t];
        p1[t] = silu_f(a);
    }
    __syncthreads();
    if (t < 4) {
        float a = 0.f;
        for (int k = 0; k < 128; k++) a += c1[k] * clW2[k * 4 + t];
        out[t] = a + clb2[t];
    }
    if (t < 128) {
        float a = 0.f;
        for (int k = 0; k < 256; k++) a += p1[k] * prW2[k * 128 + t];
        pr[t] = a + prb2[t];
    }
    __syncthreads();
    if (t == 0) {
        float s = 0.f;
        for (int k = 0; k < 128; k++) s += pr[k] * pr[k];
        nrm = fmaxf(sqrtf(s), 1e-12f);
    }
    __syncthreads();
    if (t < 128) out[4 + t] = pr[t] / nrm;
}

// ---------------- launch ----------------
extern "C" void kernel_launch(void* const* d_in, const int* in_sizes, int n_in,
                              void* d_out, int out_size) {
    const float* x       = (const float*)d_in[0];
    const float* pos     = (const float*)d_in[1];
    const int*   ei      = (const int*)d_in[2];
    const float* ne_W1   = (const float*)d_in[3];
    const float* ne_b1   = (const float*)d_in[4];
    const float* ne_W2   = (const float*)d_in[5];
    const float* ne_b2   = (const float*)d_in[6];
    const float* ne_g    = (const float*)d_in[7];
    const float* ne_beta = (const float*)d_in[8];
    const float* convW   = (const float*)d_in[9];
    const float* convB   = (const float*)d_in[10];
    const float* convG   = (const float*)d_in[11];
    const float* convBeta= (const float*)d_in[12];
    const float* lnG     = (const float*)d_in[13];
    const float* lnB     = (const float*)d_in[14];
    const float* pgW1    = (const float*)d_in[15];
    const float* pgb1    = (const float*)d_in[16];
    const float* pgW2    = (const float*)d_in[17];
    const float* pgb2    = (const float*)d_in[18];
    const float* clW1    = (const float*)d_in[19];
    const float* clb1    = (const float*)d_in[20];
    const float* clW2    = (const float*)d_in[21];
    const float* clb2    = (const float*)d_in[22];
    const float* prW1    = (const float*)d_in[23];
    const float* prb1    = (const float*)d_in[24];
    const float* prW2    = (const float*)d_in[25];
    const float* prb2    = (const float*)d_in[26];
    float* out = (float*)d_out;

    float *p_t1, *p_h, *p_Abuf, *p_agg, *p_gatev;
    float *p_W1t, *p_W2t, *p_pgW1t, *p_WpackT;
    cudaGetSymbolAddress((void**)&p_t1, g_t1);
    cudaGetSymbolAddress((void**)&p_h, g_h);
    cudaGetSymbolAddress((void**)&p_Abuf, g_Abuf);
    cudaGetSymbolAddress((void**)&p_agg, g_agg);
    cudaGetSymbolAddress((void**)&p_gatev, g_gatev);
    cudaGetSymbolAddress((void**)&p_W1t, g_W1t);
    cudaGetSymbolAddress((void**)&p_W2t, g_W2t);
    cudaGetSymbolAddress((void**)&p_pgW1t, g_pgW1t);
    cudaGetSymbolAddress((void**)&p_WpackT, g_WpackT);

    cudaFuncSetAttribute(cp_gemm_kernel, cudaFuncAttributeMaxDynamicSharedMemorySize, GEMM_DSM);

    const int EB = (EE + 255) / 256;
    const int NB = (NN + 255) / 256;
    const int WB = (NN + 7) / 8;
    const int MB = (NN + 127) / 128;
    const int SB = (NN + 1023) / 1024;

    // setup
    zero_kernel<<<NB, 256>>>();
    edge1_kernel<<<EB, 256>>>(ei);
    scan1_kernel<<<SB, 1024>>>();
    scan2_kernel<<<1, 64>>>(SB);
    scan3_kernel<<<NB, 256>>>();
    edge2_kernel<<<EB, 256>>>(ei);
    ef_kernel<<<NB, 256>>>(pos);
    trans_kernel<<<(HH * K1PAD + 255) / 256, 256>>>(ne_W1, p_W1t, NIN, HH, K1PAD);
    trans_kernel<<<(HH * HH + 255) / 256, 256>>>(ne_W2, p_W2t, HH, HH, HH);
    trans_kernel<<<(64 * HH + 255) / 256, 256>>>(pgW1, p_pgW1t, HH, 64, HH);
    packT_kernel<<<(LL * HH * KPAD + 255) / 256, 256>>>(convW, convB);

    // node encoder (GEMM1: raw x, element cp.async path + fragment cvt)
    cp_gemm_kernel<<<dim3(MB, 2), 256, GEMM_DSM>>>(x, NIN, NN, NIN, p_W1t, K1PAD, 256,
                                                   ne_b1, p_t1, HH, 1, 1, 1);
    cp_gemm_kernel<<<dim3(MB, 2), 256, GEMM_DSM>>>(p_t1, HH, NN, HH, p_W2t, HH, 256,
                                                   ne_b2, p_agg, HH, 0, 0, 0);
    ln_kernel<<<WB, 256>>>(p_agg, ne_g, ne_beta, p_h, NN);

    // conv layers
    for (int l = 0; l < LL; l++) {
        gather_kernel<<<WB, 256>>>();
        cp_gemm_kernel<<<dim3(MB, 2), 256, GEMM_DSM>>>(p_Abuf, KPAD, NN, KPAD,
                                                       p_WpackT + (long)l * HH * KPAD, KPAD, 256,
                                                       nullptr, p_agg, HH, 0, 0, 0);
        postconv_kernel<<<WB, 256>>>(convG + l * HH, convBeta + l * HH,
                                     lnG + l * HH, lnB + l * HH);
    }

    // attention pooling (A = raw h with fragment cvt)
    cp_gemm_kernel<<<dim3(MB, 1), 256, GEMM_DSM>>>(p_h, HH, NN, HH, p_pgW1t, HH, 64,
                                                   pgb1, p_gatev, 64, 1, 0, 1);
    gate_kernel<<<WB, 256>>>(pgW2, pgb2);
    maxpart_kernel<<<64, 256>>>();
    maxfin_kernel<<<1, 256>>>(64);
    expsum_kernel<<<NB, 256>>>();
    wsum_kernel<<<NB, 256>>>();

    // heads
    heads_kernel<<<1, 256>>>(clW1, clb1, clW2, clb2, prW1, prb1, prW2, prb2, out);
}

// round 8
// speedup vs baseline: 2.6687x; 1.2134x over previous
#include <cuda_runtime.h>
#include <math.h>
#include <stdint.h>

#define NN 50000
#define EE 1000000
#define NIN 1281
#define K1PAD 1312
#define HH 256
#define LL 4
#define KPAD 288            // 256 Hsum + 3 sh + 16 radial + 1 deg + 12 zero pad

// ---------------- scratch ----------------
__device__ float g_t1[NN * HH];
__device__ float g_h[NN * HH];
__device__ float g_Abuf[NN * KPAD];
__device__ float g_gatev[NN * 64];
__device__ float g_gate[NN];
__device__ int   g_deg[NN];
__device__ int   g_rowptr[NN + 1];
__device__ int   g_cursor[NN];
__device__ int   g_csrc[EE];
__device__ float g_W1t[HH * K1PAD];
__device__ float g_W2t[HH * HH];
__device__ float g_pgW1t[64 * HH];
__device__ float g_WpackT[LL * HH * KPAD];
__device__ float g_scal[4];
__device__ float g_Gvec[HH];
__device__ int   g_bsum[64];
__device__ unsigned g_amax;

// ---------------- helpers ----------------
__device__ __forceinline__ float warp_sum(float v) {
    #pragma unroll
    for (int o = 16; o; o >>= 1) v += __shfl_xor_sync(0xffffffffu, v, o);
    return v;
}
__device__ __forceinline__ float silu_f(float x) { return x / (1.f + expf(-x)); }
__device__ __forceinline__ unsigned f2tf(float f) {
    unsigned r;
    asm("cvt.rna.tf32.f32 %0, %1;" : "=r"(r) : "f"(f));
    return r;
}
__device__ __forceinline__ float f2tff(float f) { return __uint_as_float(f2tf(f)); }
__device__ __forceinline__ uint32_t smem_u32(const void* p) {
    uint32_t a;
    asm("{ .reg .u64 t; cvta.to.shared.u64 t, %1; cvt.u32.u64 %0, t; }" : "=r"(a) : "l"(p));
    return a;
}
__device__ __forceinline__ unsigned fkey(float f) {
    unsigned u = __float_as_uint(f);
    return (u & 0x80000000u) ? ~u : (u | 0x80000000u);
}
__device__ __forceinline__ float funkey(unsigned k) {
    unsigned u = (k & 0x80000000u) ? (k & 0x7fffffffu) : ~k;
    return __uint_as_float(u);
}
#define CP_ASYNC16(dst, src) \
    asm volatile("cp.async.ca.shared.global [%0], [%1], 16;" :: "r"(dst), "l"(src))
#define CP_ASYNC4Z(dst, src, sz) \
    asm volatile("cp.async.ca.shared.global [%0], [%1], 4, %2;" :: "r"(dst), "l"(src), "r"(sz))
#define CP_COMMIT() asm volatile("cp.async.commit_group;" ::: "memory")
#define CP_WAIT1()  asm volatile("cp.async.wait_group 1;" ::: "memory")

// ---------------- setup ----------------
__global__ void zero_kernel() {
    int i = blockIdx.x * 256 + threadIdx.x;
    if (i < NN) { g_deg[i] = 0; g_cursor[i] = 0; }
    if (i < HH) g_Gvec[i] = 0.f;
    if (i < 4) g_scal[i] = 0.f;
    if (i == 0) { g_rowptr[0] = 0; g_amax = 0u; }
}

__global__ void edge1_kernel(const int* __restrict__ ei) {
    int e = blockIdx.x * 256 + threadIdx.x;
    if (e >= EE) return;
    atomicAdd(&g_deg[ei[EE + e]], 1);
}

__global__ void scan1_kernel() {
    __shared__ int s[1024];
    int tid = threadIdx.x;
    int gid = blockIdx.x * 1024 + tid;
    int v = (gid < NN) ? g_deg[gid] : 0;
    s[tid] = v;
    __syncthreads();
    for (int off = 1; off < 1024; off <<= 1) {
        int t = (tid >= off) ? s[tid - off] : 0;
        __syncthreads();
        s[tid] += t;
        __syncthreads();
    }
    if (gid < NN) g_rowptr[gid + 1] = s[tid];
    if (tid == 1023) g_bsum[blockIdx.x] = s[1023];
}

// fused: scan of block sums (redundant per CTA) + add offsets
__global__ void scan3b_kernel(int nb) {
    __shared__ int pref[64];
    int tid = threadIdx.x;
    if (tid < 64) pref[tid] = (tid < nb) ? g_bsum[tid] : 0;
    __syncthreads();
    for (int off = 1; off < 64; off <<= 1) {
        int t = (tid >= off && tid < 64) ? pref[tid - off] : 0;
        __syncthreads();
        if (tid < 64) pref[tid] += t;
        __syncthreads();
    }
    int gid = blockIdx.x * 256 + tid;
    if (gid < NN) {
        int b = gid >> 10;
        if (b > 0) g_rowptr[gid + 1] += pref[b - 1];
    }
}

__global__ void edge2_kernel(const int* __restrict__ ei) {
    int e = blockIdx.x * 256 + threadIdx.x;
    if (e >= EE) return;
    int s = ei[e];
    int d = ei[EE + e];
    int slot = atomicAdd(&g_cursor[d], 1);
    g_csrc[g_rowptr[d] + slot] = s;
}

__global__ void ef_kernel(const float* __restrict__ pos) {
    int n = blockIdx.x * 256 + threadIdx.x;
    if (n >= NN) return;
    const float w = 0.1953125f;
    const float cstep = 10.f / 15.f;
    float Ej[16];
    #pragma unroll
    for (int j = 0; j < 16; j++) {
        float c = cstep * (float)j;
        Ej[j] = expf(-w * c * c);
    }
    float px = pos[3 * n + 0], py = pos[3 * n + 1], pz = pos[3 * n + 2];
    float shx = 0.f, shy = 0.f, shz = 0.f;
    float rad[16];
    #pragma unroll
    for (int j = 0; j < 16; j++) rad[j] = 0.f;
    int beg = g_rowptr[n], end = g_rowptr[n + 1];
    for (int e = beg; e < end; e++) {
        int s = g_csrc[e];
        float rx = px - pos[3 * s + 0];
        float ry = py - pos[3 * s + 1];
        float rz = pz - pos[3 * s + 2];
        float dist = sqrtf(rx * rx + ry * ry + rz * rz);
        float inv = 1.f / fmaxf(dist, 1e-12f);
        shx += rx * inv; shy += ry * inv; shz += rz * inv;
        if (dist < 18.f) {
            float A = expf(-w * dist * dist);
            float r1 = expf(2.f * w * cstep * dist);
            float r2 = r1 * r1, r4 = r2 * r2, r8 = r4 * r4;
            float p[16];
            p[0] = A;        p[1] = A * r1;
            p[2] = p[0] * r2; p[3] = p[1] * r2;
            #pragma unroll
            for (int j = 0; j < 4; j++) p[4 + j] = p[j] * r4;
            #pragma unroll
            for (int j = 0; j < 8; j++) p[8 + j] = p[j] * r8;
            #pragma unroll
            for (int j = 0; j < 16; j++) rad[j] += p[j] * Ej[j];
        } else {
            #pragma unroll
            for (int j = 0; j < 16; j++) {
                float t = dist - cstep * (float)j;
                rad[j] += expf(-w * t * t);
            }
        }
    }
    float* ab = g_Abuf + (long)n * KPAD + 256;
    ab[0] = f2tff(shx); ab[1] = f2tff(shy); ab[2] = f2tff(shz);
    #pragma unroll
    for (int j = 0; j < 16; j++) ab[3 + j] = f2tff(rad[j]);
    ab[19] = (float)(end - beg);
    #pragma unroll
    for (int j = 20; j < 32; j++) ab[j] = 0.f;
}

__global__ void trans_kernel(const float* __restrict__ src, float* __restrict__ dst,
                             int K, int N, int kpad) {
    int idx = blockIdx.x * 256 + threadIdx.x;
    if (idx >= N * kpad) return;
    int n = idx / kpad, k = idx % kpad;
    float v = (k < K) ? src[(long)k * N + n] : 0.f;
    dst[idx] = f2tff(v);
}

__global__ void packT_kernel(const float* __restrict__ convW, const float* __restrict__ convB) {
    int idx = blockIdx.x * 256 + threadIdx.x;
    const int total = LL * HH * KPAD;
    if (idx >= total) return;
    int l = idx / (HH * KPAD);
    int rem = idx % (HH * KPAD);
    int n = rem / KPAD;
    int k = rem % KPAD;
    float v = 0.f;
    if (k < 275)       v = convW[((long)l * 275 + k) * HH + n];
    else if (k == 275) v = convB[l * HH + n];
    g_WpackT[idx] = f2tff(v);
}

// ================= big GEMM: 512 threads, 128x256 tile, fused epilogues =================
// mode 0: C = silu(acc + bias)                        (direct stores)
// mode 1: hbuf = LN(acc + bias; p1,p2)                (smem tile epilogue)
// mode 2: hbuf = LN(hbuf + LN(silu(acc); p1,p2); p3,p4)
#define AST 36
#define STG2_FLTS ((128 + 256) * AST)          // 13824 floats/stage
#define BG_DSM (3 * STG2_FLTS * 4)             // 165888 bytes
#define EPI_ST 258
__global__ __launch_bounds__(512, 1)
void big_gemm_kernel(const float* __restrict__ A, int lda, int M, int K,
                     const float* __restrict__ Bt, int ldb,
                     const float* __restrict__ bias,
                     float* __restrict__ C, int ldc,
                     int mode, int cvtA,
                     const float* __restrict__ p1, const float* __restrict__ p2,
                     const float* __restrict__ p3, const float* __restrict__ p4,
                     float* __restrict__ hbuf) {
    extern __shared__ float sm[];
    int t = threadIdx.x;
    int lane = t & 31, warp = t >> 5;     // 16 warps
    int wr = warp >> 3;                   // 0..1 (64-row bands)
    int wc = warp & 7;                    // 0..7 (32-col bands)
    int rowBase = blockIdx.x * 128;
    uint32_t smb = smem_u32(sm);

    int nT = (K + 31) >> 5;
    int aElem = (lda & 3) != 0;

    float acc[4][4][4];
    #pragma unroll
    for (int mi = 0; mi < 4; mi++)
        #pragma unroll
        for (int ni = 0; ni < 4; ni++)
            #pragma unroll
            for (int q = 0; q < 4; q++) acc[mi][ni][q] = 0.f;

    auto load_stage = [&](int i, int s) {
        int k0 = i << 5;
        uint32_t sbase = smb + (uint32_t)(s * STG2_FLTS) * 4u;
        if (aElem) {
            #pragma unroll
            for (int it = 0; it < 2; it++) {
                int c = it * 512 + t;
                int row = c >> 3, cq = c & 7;
                int gr = rowBase + row;
                if (gr >= M) gr = M - 1;
                long rb = (long)gr * lda;
                uint32_t dst = sbase + (uint32_t)(row * AST + cq * 4) * 4u;
                #pragma unroll
                for (int j = 0; j < 4; j++) {
                    int gk = k0 + cq * 4 + j;
                    int ck = (gk < K) ? gk : (K - 1);
                    int sz = (gk < K) ? 4 : 0;
                    CP_ASYNC4Z(dst + j * 4, A + rb + ck, sz);
                }
            }
        } else {
            #pragma unroll
            for (int it = 0; it < 2; it++) {
                int c = it * 512 + t;
                int row = c >> 3, cq = c & 7;
                int gr = rowBase + row;
                if (gr >= M) gr = M - 1;
                const float* src = A + (long)gr * lda + k0 + cq * 4;
                uint32_t dst = sbase + (uint32_t)(row * AST + cq * 4) * 4u;
                CP_ASYNC16(dst, src);
            }
        }
        #pragma unroll
        for (int it = 0; it < 4; it++) {
            int c = it * 512 + t;
            int n = c >> 3, cq = c & 7;
            const float* src = Bt + (long)n * ldb + k0 + cq * 4;
            uint32_t dst = sbase + (uint32_t)(128 * AST + n * AST + cq * 4) * 4u;
            CP_ASYNC16(dst, src);
        }
    };

    load_stage(0, 0);
    CP_COMMIT();
    if (nT > 1) load_stage(1, 1);
    CP_COMMIT();

    int kq = lane & 3;
    int kg = lane >> 2;

    for (int i = 0; i < nT; i++) {
        CP_WAIT1();
        __syncthreads();
        if (i + 2 < nT) load_stage(i + 2, (i + 2) % 3);
        CP_COMMIT();

        const float* As = sm + (i % 3) * STG2_FLTS;
        const float* Bs = As + 128 * AST;
        #pragma unroll
        for (int kk = 0; kk < 4; kk++) {
            int ko = kk * 8;
            unsigned af[4][4], bf[4][2];
            #pragma unroll
            for (int mi = 0; mi < 4; mi++) {
                int ar = wr * 64 + mi * 16 + kg;
                af[mi][0] = __float_as_uint(As[ar * AST + ko + kq]);
                af[mi][1] = __float_as_uint(As[(ar + 8) * AST + ko + kq]);
                af[mi][2] = __float_as_uint(As[ar * AST + ko + kq + 4]);
                af[mi][3] = __float_as_uint(As[(ar + 8) * AST + ko + kq + 4]);
            }
            if (cvtA) {
                #pragma unroll
                for (int mi = 0; mi < 4; mi++)
                    #pragma unroll
                    for (int q = 0; q < 4; q++)
                        af[mi][q] = f2tf(__uint_as_float(af[mi][q]));
            }
            #pragma unroll
            for (int ni = 0; ni < 4; ni++) {
                int bn = wc * 32 + ni * 8 + kg;
                bf[ni][0] = __float_as_uint(Bs[bn * AST + ko + kq]);
                bf[ni][1] = __float_as_uint(Bs[bn * AST + ko + kq + 4]);
            }
            #pragma unroll
            for (int mi = 0; mi < 4; mi++)
                #pragma unroll
                for (int ni = 0; ni < 4; ni++) {
                    asm volatile(
                        "mma.sync.aligned.m16n8k8.row.col.f32.tf32.tf32.f32 "
                        "{%0,%1,%2,%3}, {%4,%5,%6,%7}, {%8,%9}, {%0,%1,%2,%3};"
                        : "+f"(acc[mi][ni][0]), "+f"(acc[mi][ni][1]),
                          "+f"(acc[mi][ni][2]), "+f"(acc[mi][ni][3])
                        : "r"(af[mi][0]), "r"(af[mi][1]), "r"(af[mi][2]), "r"(af[mi][3]),
                          "r"(bf[ni][0]), "r"(bf[ni][1]));
                }
        }
    }

    if (mode == 0) {
        // direct stores with silu
        #pragma unroll
        for (int mi = 0; mi < 4; mi++) {
            #pragma unroll
            for (int ni = 0; ni < 4; ni++) {
                int r0 = rowBase + wr * 64 + mi * 16 + kg;
                int c0 = wc * 32 + ni * 8 + kq * 2;
                #pragma unroll
                for (int half = 0; half < 2; half++) {
                    int r = r0 + half * 8;
                    if (r >= M) continue;
                    #pragma unroll
                    for (int q = 0; q < 2; q++) {
                        int c = c0 + q;
                        float v = acc[mi][ni][half * 2 + q] + (bias ? bias[c] : 0.f);
                        C[(long)r * ldc + c] = silu_f(v);
                    }
                }
            }
        }
        return;
    }

    // smem-tile epilogue (modes 1,2): full rows in CTA
    __syncthreads();   // all LDS from stage buffers done before overwrite
    #pragma unroll
    for (int mi = 0; mi < 4; mi++) {
        #pragma unroll
        for (int ni = 0; ni < 4; ni++) {
            int rloc0 = wr * 64 + mi * 16 + kg;
            int c0 = wc * 32 + ni * 8 + kq * 2;
            #pragma unroll
            for (int half = 0; half < 2; half++) {
                int rl = rloc0 + half * 8;
                #pragma unroll
                for (int q = 0; q < 2; q++) {
                    int c = c0 + q;
                    float v = acc[mi][ni][half * 2 + q] + (bias ? bias[c] : 0.f);
                    sm[rl * EPI_ST + c] = v;
                }
            }
        }
    }
    __syncthreads();

    #pragma unroll
    for (int rr = 0; rr < 8; rr++) {
        int rl = rr * 16 + warp;
        int gr = rowBase + rl;
        if (gr >= M) continue;
        float x[8];
        #pragma unroll
        for (int i = 0; i < 8; i++) x[i] = sm[rl * EPI_ST + lane + 32 * i];
        if (mode == 1) {
            float s = 0.f;
            #pragma unroll
            for (int i = 0; i < 8; i++) s += x[i];
            s = warp_sum(s);
            float m = s * (1.f / 256.f);
            float qv = 0.f;
            #pragma unroll
            for (int i = 0; i < 8; i++) { float d = x[i] - m; qv += d * d; }
            qv = warp_sum(qv);
            float rs = rsqrtf(qv * (1.f / 256.f) + 1e-5f);
            float* op = hbuf + (long)gr * HH;
            #pragma unroll
            for (int i = 0; i < 8; i++) {
                int c = lane + 32 * i;
                op[c] = (x[i] - m) * rs * p1[c] + p2[c];
            }
        } else {
            // mode 2: postconv
            float* hp = hbuf + (long)gr * HH;
            float s = 0.f;
            #pragma unroll
            for (int i = 0; i < 8; i++) { x[i] = silu_f(x[i]); s += x[i]; }
            s = warp_sum(s);
            float m1 = s * (1.f / 256.f);
            float qv = 0.f;
            #pragma unroll
            for (int i = 0; i < 8; i++) { float d = x[i] - m1; qv += d * d; }
            qv = warp_sum(qv);
            float rs1 = rsqrtf(qv * (1.f / 256.f) + 1e-5f);
            float z[8];
            float s2 = 0.f;
            #pragma unroll
            for (int i = 0; i < 8; i++) {
                int c = lane + 32 * i;
                float y = (x[i] - m1) * rs1 * p1[c] + p2[c];
                float zz = hp[c] + y;
                z[i] = zz; s2 += zz;
            }
            s2 = warp_sum(s2);
            float m2 = s2 * (1.f / 256.f);
            float q2 = 0.f;
            #pragma unroll
            for (int i = 0; i < 8; i++) { float d = z[i] - m2; q2 += d * d; }
            q2 = warp_sum(q2);
            float rs2 = rsqrtf(q2 * (1.f / 256.f) + 1e-5f);
            #pragma unroll
            for (int i = 0; i < 8; i++) {
                int c = lane + 32 * i;
                hp[c] = (z[i] - m2) * rs2 * p3[c] + p4[c];
            }
        }
    }
}

// ================= small GEMM (256 thr) for pool gate =================
#define STG_FLTS (2 * 128 * AST)
#define GEMM_DSM (3 * STG_FLTS * 4)
__global__ __launch_bounds__(256, 2)
void cp_gemm_kernel(const float* __restrict__ A, int lda, int M, int K,
                    const float* __restrict__ Bt, int ldb, int Nt,
                    const float* __restrict__ bias, float* __restrict__ C, int ldc,
                    int act, int cvtA) {
    extern __shared__ float sm[];
    int t = threadIdx.x;
    int lane = t & 31, warp = t >> 5;
    int wr = warp >> 2;
    int wc = warp & 3;
    int rowBase = blockIdx.x * 128;
    int colBase = blockIdx.y * 128;
    uint32_t smb = smem_u32(sm);

    int nT = (K + 31) >> 5;
    int bRows = (Nt < 128) ? Nt : 128;
    int bChunks = bRows * 8;

    float acc[4][4][4];
    #pragma unroll
    for (int mi = 0; mi < 4; mi++)
        #pragma unroll
        for (int ni = 0; ni < 4; ni++)
            #pragma unroll
            for (int q = 0; q < 4; q++) acc[mi][ni][q] = 0.f;

    auto load_stage = [&](int i, int s) {
        int k0 = i << 5;
        uint32_t sbase = smb + (uint32_t)(s * STG_FLTS) * 4u;
        #pragma unroll
        for (int it = 0; it < 4; it++) {
            int c = it * 256 + t;
            int row = c >> 3, cq = c & 7;
            int gr = rowBase + row;
            if (gr >= M) gr = M - 1;
            const float* src = A + (long)gr * lda + k0 + cq * 4;
            uint32_t dst = sbase + (uint32_t)(row * AST + cq * 4) * 4u;
            CP_ASYNC16(dst, src);
        }
        for (int c = t; c < bChunks; c += 256) {
            int n = c >> 3, cq = c & 7;
            const float* src = Bt + (long)(colBase + n) * ldb + k0 + cq * 4;
            uint32_t dst = sbase + (uint32_t)(128 * AST + n * AST + cq * 4) * 4u;
            CP_ASYNC16(dst, src);
        }
    };

    load_stage(0, 0);
    CP_COMMIT();
    if (nT > 1) load_stage(1, 1);
    CP_COMMIT();

    int kq = lane & 3;
    int kg = lane >> 2;

    for (int i = 0; i < nT; i++) {
        CP_WAIT1();
        __syncthreads();
        if (i + 2 < nT) load_stage(i + 2, (i + 2) % 3);
        CP_COMMIT();

        const float* As = sm + (i % 3) * STG_FLTS;
        const float* Bs = As + 128 * AST;
        #pragma unroll
        for (int kk = 0; kk < 4; kk++) {
            int ko = kk * 8;
            unsigned af[4][4], bf[4][2];
            #pragma unroll
            for (int mi = 0; mi < 4; mi++) {
                int ar = wr * 64 + mi * 16 + kg;
                af[mi][0] = __float_as_uint(As[ar * AST + ko + kq]);
                af[mi][1] = __float_as_uint(As[(ar + 8) * AST + ko + kq]);
                af[mi][2] = __float_as_uint(As[ar * AST + ko + kq + 4]);
                af[mi][3] = __float_as_uint(As[(ar + 8) * AST + ko + kq + 4]);
            }
            if (cvtA) {
                #pragma unroll
                for (int mi = 0; mi < 4; mi++)
                    #pragma unroll
                    for (int q = 0; q < 4; q++)
                        af[mi][q] = f2tf(__uint_as_float(af[mi][q]));
            }
            #pragma unroll
            for (int ni = 0; ni < 4; ni++) {
                int bn = wc * 32 + ni * 8 + kg;
                bf[ni][0] = __float_as_uint(Bs[bn * AST + ko + kq]);
                bf[ni][1] = __float_as_uint(Bs[bn * AST + ko + kq + 4]);
            }
            #pragma unroll
            for (int mi = 0; mi < 4; mi++)
                #pragma unroll
                for (int ni = 0; ni < 4; ni++) {
                    asm volatile(
                        "mma.sync.aligned.m16n8k8.row.col.f32.tf32.tf32.f32 "
                        "{%0,%1,%2,%3}, {%4,%5,%6,%7}, {%8,%9}, {%0,%1,%2,%3};"
                        : "+f"(acc[mi][ni][0]), "+f"(acc[mi][ni][1]),
                          "+f"(acc[mi][ni][2]), "+f"(acc[mi][ni][3])
                        : "r"(af[mi][0]), "r"(af[mi][1]), "r"(af[mi][2]), "r"(af[mi][3]),
                          "r"(bf[ni][0]), "r"(bf[ni][1]));
                }
        }
    }

    #pragma unroll
    for (int mi = 0; mi < 4; mi++) {
        #pragma unroll
        for (int ni = 0; ni < 4; ni++) {
            int r0 = rowBase + wr * 64 + mi * 16 + kg;
            int c0 = colBase + wc * 32 + ni * 8 + kq * 2;
            #pragma unroll
            for (int half = 0; half < 2; half++) {
                int r = r0 + half * 8;
                if (r >= M) continue;
                #pragma unroll
                for (int q = 0; q < 2; q++) {
                    int c = c0 + q;
                    if (c >= Nt) continue;
                    float v = acc[mi][ni][half * 2 + q] + (bias ? bias[c] : 0.f);
                    if (act) v = silu_f(v);
                    C[(long)r * ldc + c] = v;
                }
            }
        }
    }
}

// ---------------- gather ----------------
__global__ void gather_kernel() {
    int w = (blockIdx.x * 256 + threadIdx.x) >> 5;
    int lane = threadIdx.x & 31;
    if (w >= NN) return;
    float4 a0 = make_float4(0.f, 0.f, 0.f, 0.f);
    float4 a1 = make_float4(0.f, 0.f, 0.f, 0.f);
    float4 c0 = make_float4(0.f, 0.f, 0.f, 0.f);
    float4 c1 = make_float4(0.f, 0.f, 0.f, 0.f);
    int beg = g_rowptr[w], end = g_rowptr[w + 1];
    int e = beg;
    for (; e + 1 < end; e += 2) {
        int s0 = g_csrc[e];
        int s1 = g_csrc[e + 1];
        const float4* h0 = (const float4*)(g_h + (long)s0 * HH);
        const float4* h1 = (const float4*)(g_h + (long)s1 * HH);
        float4 v0 = h0[lane];
        float4 v1 = h0[lane + 32];
        float4 u0 = h1[lane];
        float4 u1 = h1[lane + 32];
        a0.x += v0.x; a0.y += v0.y; a0.z += v0.z; a0.w += v0.w;
        a1.x += v1.x; a1.y += v1.y; a1.z += v1.z; a1.w += v1.w;
        c0.x += u0.x; c0.y += u0.y; c0.z += u0.z; c0.w += u0.w;
        c1.x += u1.x; c1.y += u1.y; c1.z += u1.z; c1.w += u1.w;
    }
    if (e < end) {
        int s0 = g_csrc[e];
        const float4* h0 = (const float4*)(g_h + (long)s0 * HH);
        float4 v0 = h0[lane];
        float4 v1 = h0[lane + 32];
        a0.x += v0.x; a0.y += v0.y; a0.z += v0.z; a0.w += v0.w;
        a1.x += v1.x; a1.y += v1.y; a1.z += v1.z; a1.w += v1.w;
    }
    a0.x = f2tff(a0.x + c0.x); a0.y = f2tff(a0.y + c0.y);
    a0.z = f2tff(a0.z + c0.z); a0.w = f2tff(a0.w + c0.w);
    a1.x = f2tff(a1.x + c1.x); a1.y = f2tff(a1.y + c1.y);
    a1.z = f2tff(a1.z + c1.z); a1.w = f2tff(a1.w + c1.w);
    float4* ap = (float4*)(g_Abuf + (long)w * KPAD);
    ap[lane] = a0;
    ap[lane + 32] = a1;
}

// ---------------- pooling (merged) ----------------
__global__ void gatemax_kernel(const float* __restrict__ pgW2, const float* __restrict__ pgb2) {
    __shared__ float warpmax[8];
    int tid = threadIdx.x;
    int w = (blockIdx.x * 256 + tid) >> 5;
    int lane = tid & 31;
    int wid = tid >> 5;
    float gate = -1e30f;
    if (w < NN) {
        float v = g_gatev[(long)w * 64 + lane] * pgW2[lane]
                + g_gatev[(long)w * 64 + 32 + lane] * pgW2[32 + lane];
        v = warp_sum(v);
        gate = v + pgb2[0];
        if (lane == 0) g_gate[w] = gate;
    }
    if (lane == 0) warpmax[wid] = gate;
    __syncthreads();
    if (tid == 0) {
        float m = warpmax[0];
        #pragma unroll
        for (int j = 1; j < 8; j++) m = fmaxf(m, warpmax[j]);
        atomicMax(&g_amax, fkey(m));
    }
}

__global__ void expwsum_kernel() {
    __shared__ float e[256];
    __shared__ float red[256];
    int tid = threadIdx.x;
    int n = blockIdx.x * 256 + tid;
    float M = funkey(g_amax);
    float ev = 0.f;
    if (n < NN) ev = expf(g_gate[n] - M);
    e[tid] = ev;
    red[tid] = ev;
    __syncthreads();
    for (int o = 128; o; o >>= 1) {
        if (tid < o) red[tid] += red[tid + o];
        __syncthreads();
    }
    if (tid == 0) atomicAdd(&g_scal[1], red[0]);
    // weighted sum: thread = column
    float acc = 0.f;
    int n0 = blockIdx.x * 256;
    for (int i = 0; i < 256; i++) {
        int nn = n0 + i;
        if (nn >= NN) break;
        acc += e[i] * g_h[(long)nn * HH + tid];
    }
    atomicAdd(&g_Gvec[tid], acc);
}

// ---------------- heads ----------------
__global__ void heads_kernel(const float* __restrict__ clW1, const float* __restrict__ clb1,
                             const float* __restrict__ clW2, const float* __restrict__ clb2,
                             const float* __restrict__ prW1, const float* __restrict__ prb1,
                             const float* __restrict__ prW2, const float* __restrict__ prb2,
                             float* __restrict__ out) {
    __shared__ float emb[256], c1[128], p1[256], pr[128];
    __shared__ float nrm;
    int t = threadIdx.x;
    float se = g_scal[1];
    float ev = g_Gvec[t] / se;
    emb[t] = ev;
    out[132 + t] = ev;
    __syncthreads();
    if (t < 128) {
        float a = 0.f;
        for (int k = 0; k < 256; k++) a += emb[k] * clW1[k * 128 + t];
        a += clb1[t];
        c1[t] = silu_f(a);
    }
    {
        float a = 0.f;
        for (int k = 0; k < 256; k++) a += emb[k] * prW1[k * 256 + t];
        a += prb1[t];
        p1[t] = silu_f(a);
    }
    __syncthreads();
    if (t < 4) {
        float a = 0.f;
        for (int k = 0; k < 128; k++) a += c1[k] * clW2[k * 4 + t];
        out[t] = a + clb2[t];
    }
    if (t < 128) {
        float a = 0.f;
        for (int k = 0; k < 256; k++) a += p1[k] * prW2[k * 128 + t];
        pr[t] = a + prb2[t];
    }
    __syncthreads();
    if (t == 0) {
        float s = 0.f;
        for (int k = 0; k < 128; k++) s += pr[k] * pr[k];
        nrm = fmaxf(sqrtf(s), 1e-12f);
    }
    __syncthreads();
    if (t < 128) out[4 + t] = pr[t] / nrm;
}

// ---------------- launch ----------------
extern "C" void kernel_launch(void* const* d_in, const int* in_sizes, int n_in,
                              void* d_out, int out_size) {
    const float* x       = (const float*)d_in[0];
    const float* pos     = (const float*)d_in[1];
    const int*   ei      = (const int*)d_in[2];
    const float* ne_W1   = (const float*)d_in[3];
    const float* ne_b1   = (const float*)d_in[4];
    const float* ne_W2   = (const float*)d_in[5];
    const float* ne_b2   = (const float*)d_in[6];
    const float* ne_g    = (const float*)d_in[7];
    const float* ne_beta = (const float*)d_in[8];
    const float* convW   = (const float*)d_in[9];
    const float* convB   = (const float*)d_in[10];
    const float* convG   = (const float*)d_in[11];
    const float* convBeta= (const float*)d_in[12];
    const float* lnG     = (const float*)d_in[13];
    const float* lnB     = (const float*)d_in[14];
    const float* pgW1    = (const float*)d_in[15];
    const float* pgb1    = (const float*)d_in[16];
    const float* pgW2    = (const float*)d_in[17];
    const float* pgb2    = (const float*)d_in[18];
    const float* clW1    = (const float*)d_in[19];
    const float* clb1    = (const float*)d_in[20];
    const float* clW2    = (const float*)d_in[21];
    const float* clb2    = (const float*)d_in[22];
    const float* prW1    = (const float*)d_in[23];
    const float* prb1    = (const float*)d_in[24];
    const float* prW2    = (const float*)d_in[25];
    const float* prb2    = (const float*)d_in[26];
    float* out = (float*)d_out;

    float *p_t1, *p_h, *p_Abuf, *p_gatev;
    float *p_W1t, *p_W2t, *p_pgW1t, *p_WpackT;
    cudaGetSymbolAddress((void**)&p_t1, g_t1);
    cudaGetSymbolAddress((void**)&p_h, g_h);
    cudaGetSymbolAddress((void**)&p_Abuf, g_Abuf);
    cudaGetSymbolAddress((void**)&p_gatev, g_gatev);
    cudaGetSymbolAddress((void**)&p_W1t, g_W1t);
    cudaGetSymbolAddress((void**)&p_W2t, g_W2t);
    cudaGetSymbolAddress((void**)&p_pgW1t, g_pgW1t);
    cudaGetSymbolAddress((void**)&p_WpackT, g_WpackT);

    cudaFuncSetAttribute(big_gemm_kernel, cudaFuncAttributeMaxDynamicSharedMemorySize, BG_DSM);
    cudaFuncSetAttribute(cp_gemm_kernel, cudaFuncAttributeMaxDynamicSharedMemorySize, GEMM_DSM);

    const int EB = (EE + 255) / 256;
    const int NB = (NN + 255) / 256;
    const int WB = (NN + 7) / 8;
    const int MB = (NN + 127) / 128;
    const int SB = (NN + 1023) / 1024;

    // setup
    zero_kernel<<<NB, 256>>>();
    edge1_kernel<<<EB, 256>>>(ei);
    scan1_kernel<<<SB, 1024>>>();
    scan3b_kernel<<<NB, 256>>>(SB);
    edge2_kernel<<<EB, 256>>>(ei);
    ef_kernel<<<NB, 256>>>(pos);
    trans_kernel<<<(HH * K1PAD + 255) / 256, 256>>>(ne_W1, p_W1t, NIN, HH, K1PAD);
    trans_kernel<<<(HH * HH + 255) / 256, 256>>>(ne_W2, p_W2t, HH, HH, HH);
    trans_kernel<<<(64 * HH + 255) / 256, 256>>>(pgW1, p_pgW1t, HH, 64, HH);
    packT_kernel<<<(LL * HH * KPAD + 255) / 256, 256>>>(convW, convB);

    // node encoder: GEMM1 (silu), GEMM2 (+fused LN -> h)
    big_gemm_kernel<<<MB, 512, BG_DSM>>>(x, NIN, NN, NIN, p_W1t, K1PAD,
                                         ne_b1, p_t1, HH, 0, 1,
                                         nullptr, nullptr, nullptr, nullptr, nullptr);
    big_gemm_kernel<<<MB, 512, BG_DSM>>>(p_t1, HH, NN, HH, p_W2t, HH,
                                         ne_b2, nullptr, HH, 1, 0,
                                         ne_g, ne_beta, nullptr, nullptr, p_h);

    // conv layers: gather + GEMM(+fused postconv -> h)
    for (int l = 0; l < LL; l++) {
        gather_kernel<<<WB, 256>>>();
        big_gemm_kernel<<<MB, 512, BG_DSM>>>(p_Abuf, KPAD, NN, KPAD,
                                             p_WpackT + (long)l * HH * KPAD, KPAD,
                                             nullptr, nullptr, HH, 2, 0,
                                             convG + l * HH, convBeta + l * HH,
                                             lnG + l * HH, lnB + l * HH, p_h);
    }

    // attention pooling
    cp_gemm_kernel<<<dim3(MB, 1), 256, GEMM_DSM>>>(p_h, HH, NN, HH, p_pgW1t, HH, 64,
                                                   pgb1, p_gatev, 64, 1, 1);
    gatemax_kernel<<<WB, 256>>>(pgW2, pgb2);
    expwsum_kernel<<<NB, 256>>>();

    // heads
    heads_kernel<<<1, 256>>>(clW1, clb1, clW2, clb2, prW1, prb1, prW2, prb2, out);
}